// round 9
// baseline (speedup 1.0000x reference)
#include <cuda_runtime.h>
#include <cuda_fp16.h>
#include <cstdint>

#define E_ 8
#define D_ 512
#define F_ 2048
#define N_ 4096
#define KSPLIT 2

#define BK 16                      // k halves per stage
#define NSTG 5

#define A_ROWS 128
#define A_STRIDE 24                // halves (48B rows, LDSM conflict-free)
#define B_ROWS 16
#define B_STRIDE 136               // halves (272B rows, LDSM conflict-free)

#define ASTAGE_B (A_ROWS * A_STRIDE * 2)        // 6144 bytes
#define BSTAGE_B (B_ROWS * B_STRIDE * 2)        // 4352 bytes
#define B_BASE_B (NSTG * ASTAGE_B)              // 30720
#define SMEM_TOTAL_B (B_BASE_B + NSTG * BSTAGE_B)   // 52480

#define WSZ ((size_t)E_ * D_ * F_)
#define XSZ ((size_t)N_ * D_)

// ---------------- scratch (no allocations allowed) ----------------
__device__ int g_counts[E_];
__device__ int g_expert[N_];
__device__ int g_pos[N_];
__device__ int g_row2tok[N_];
__device__ int g_rowexpert[N_];
__device__ __align__(16) __half g_W1h[WSZ];            // W1 natural [e][d][f], fp16
__device__ __align__(16) __half g_W2h[WSZ];            // W2 natural [e][f][d], fp16
__device__ __align__(16) __half g_xh[XSZ];             // x fp16
__device__ __align__(16) __half g_H[(size_t)N_ * F_];  // hidden fp16
__device__ __align__(16) float  g_part[KSPLIT][(size_t)N_ * D_];

// ---------------- helpers ----------------
__device__ __forceinline__ int imin(int a, int b) { return a < b ? a : b; }

__device__ __forceinline__ void cp_async16_s(uint32_t sm, const void* gm) {
    asm volatile("cp.async.cg.shared.global [%0], [%1], 16;" :: "r"(sm), "l"(gm));
}
__device__ __forceinline__ void cp_commit() { asm volatile("cp.async.commit_group;"); }
__device__ __forceinline__ void cp_wait3()  { asm volatile("cp.async.wait_group 3;"); }

__device__ __forceinline__ void ldsm_x4(uint32_t r[4], uint32_t addr) {
    asm volatile("ldmatrix.sync.aligned.m8n8.x4.shared.b16 {%0,%1,%2,%3}, [%4];"
                 : "=r"(r[0]), "=r"(r[1]), "=r"(r[2]), "=r"(r[3]) : "r"(addr));
}
__device__ __forceinline__ void ldsm_x4_t(uint32_t r[4], uint32_t addr) {
    asm volatile("ldmatrix.sync.aligned.m8n8.x4.trans.shared.b16 {%0,%1,%2,%3}, [%4];"
                 : "=r"(r[0]), "=r"(r[1]), "=r"(r[2]), "=r"(r[3]) : "r"(addr));
}

__device__ __forceinline__ void mma_f16(float c[4], const uint32_t a[4],
                                        uint32_t b0, uint32_t b1) {
    asm volatile(
        "mma.sync.aligned.m16n8k16.row.col.f32.f16.f16.f32 "
        "{%0,%1,%2,%3}, {%4,%5,%6,%7}, {%8,%9}, {%0,%1,%2,%3};"
        : "+f"(c[0]), "+f"(c[1]), "+f"(c[2]), "+f"(c[3])
        : "r"(a[0]), "r"(a[1]), "r"(a[2]), "r"(a[3]), "r"(b0), "r"(b1));
}

__device__ __forceinline__ int expert_off(int e) {
    int s = 0;
#pragma unroll
    for (int i = 0; i < E_; i++) if (i < e) s += g_counts[i];
    return s;
}

// ---------------- prep: streaming fp16 convert of W1, W2 + counts init ----------
__global__ void prep_kernel(const float* __restrict__ W1, const float* __restrict__ W2) {
    if (blockIdx.x == 0 && threadIdx.x < E_) g_counts[threadIdx.x] = 0;
    const size_t n1 = WSZ / 4;
    const size_t total = 2 * n1;
    size_t stride = (size_t)gridDim.x * blockDim.x;
    for (size_t i = (size_t)blockIdx.x * blockDim.x + threadIdx.x; i < total; i += stride) {
        const float4* src; __half* dst; size_t j;
        if (i < n1) { src = (const float4*)W1; dst = g_W1h; j = i; }
        else        { src = (const float4*)W2; dst = g_W2h; j = i - n1; }
        float4 v = src[j];
        __half2 h0 = __floats2half2_rn(v.x, v.y);
        __half2 h1 = __floats2half2_rn(v.z, v.w);
        reinterpret_cast<uint2*>(dst)[j] = make_uint2(*(uint32_t*)&h0, *(uint32_t*)&h1);
    }
}

// ---------------- gate + x fp16 convert (fused single pass over x) ----------------
__global__ void gate_cvt_kernel(const float* __restrict__ x,
                                const float* __restrict__ Wg,
                                const float* __restrict__ bg) {
    int tok  = (blockIdx.x * blockDim.x + threadIdx.x) >> 5;
    int lane = threadIdx.x & 31;
    if (tok >= N_) return;
    const float4* xr = reinterpret_cast<const float4*>(x) + (size_t)tok * (D_ / 4);
    uint2* xo = reinterpret_cast<uint2*>(g_xh) + (size_t)tok * (D_ / 4);

    float acc[E_];
#pragma unroll
    for (int e = 0; e < E_; e++) acc[e] = 0.f;

#pragma unroll
    for (int q = 0; q < 4; q++) {
        int d4 = lane + q * 32;
        float4 v = xr[d4];
        __half2 h0 = __floats2half2_rn(v.x, v.y);
        __half2 h1 = __floats2half2_rn(v.z, v.w);
        xo[d4] = make_uint2(*(uint32_t*)&h0, *(uint32_t*)&h1);
        float vv[4] = {v.x, v.y, v.z, v.w};
#pragma unroll
        for (int t = 0; t < 4; t++) {
            const float4* w = reinterpret_cast<const float4*>(Wg + (size_t)(d4 * 4 + t) * E_);
            float4 w0 = w[0], w1 = w[1];
            acc[0] += vv[t] * w0.x; acc[1] += vv[t] * w0.y;
            acc[2] += vv[t] * w0.z; acc[3] += vv[t] * w0.w;
            acc[4] += vv[t] * w1.x; acc[5] += vv[t] * w1.y;
            acc[6] += vv[t] * w1.z; acc[7] += vv[t] * w1.w;
        }
    }
#pragma unroll
    for (int off = 16; off > 0; off >>= 1)
#pragma unroll
        for (int e = 0; e < E_; e++)
            acc[e] += __shfl_down_sync(0xFFFFFFFFu, acc[e], off);
    if (lane == 0) {
        float best = acc[0] + bg[0];
        int bi = 0;
#pragma unroll
        for (int e = 1; e < E_; e++) {
            float v = acc[e] + bg[e];
            if (v > best) { best = v; bi = e; }
        }
        int p = atomicAdd(&g_counts[bi], 1);
        g_expert[tok] = bi;
        g_pos[tok]    = p;
    }
}

// ---------------- assign compacted rows ----------------
__global__ void assign_kernel() {
    int t = blockIdx.x * blockDim.x + threadIdx.x;
    if (t >= N_) return;
    int e = g_expert[t];
    int r = expert_off(e) + g_pos[t];
    g_row2tok[r]   = t;
    g_rowexpert[r] = e;
}

// =====================================================================
// fp16 GEMM core: 256 thr, 8 warps (2x4), warp tile 64x32 = 4x4 m16n8k16.
// A smem [128][24] halves (row=m, k contig); B smem [16][136] (row=k, n contig).
// Fragments via ldmatrix: A 4x LDSM.x4, B 2x LDSM.x4.trans per k16 iter.
// 5-stage cp.async ring, wait_group 3 (prefetch distance 4 iters),
// one __syncthreads per iter. CWIDTH = B gmem row width. Dynamic smem.
// =====================================================================
#define GEMM_CORE(NK, CWIDTH)                                                     \
    extern __shared__ __align__(16) char smem_raw[];                              \
    const int lane = tid & 31;                                                    \
    const int warp = tid >> 5;                                                    \
    const int wm   = warp >> 2;        /* 0..1 */                                 \
    const int wn   = warp & 3;         /* 0..3 */                                 \
    const uint32_t sA0 = (uint32_t)__cvta_generic_to_shared(smem_raw);            \
    const uint32_t sB0 = sA0 + B_BASE_B;                                          \
    /* per-thread load slots */                                                   \
    const int la_row = tid >> 1;                                                  \
    const int la_kc  = (tid & 1) * 8;                                             \
    const int lb_k   = tid >> 4;                                                  \
    const int lb_nc  = (tid & 15) * 8;                                            \
    const uint32_t dstA = sA0 + (la_row * A_STRIDE + la_kc) * 2;                  \
    const uint32_t dstB = sB0 + (lb_k * B_STRIDE + lb_nc) * 2;                    \
    /* fragment smem addresses (constant per thread) */                           \
    uint32_t adA[4], adB[2];                                                      \
    _Pragma("unroll")                                                             \
    for (int mt = 0; mt < 4; mt++)                                                \
        adA[mt] = sA0 + (((wm * 64 + mt * 16 + (lane & 15)) * A_STRIDE            \
                          + (lane >> 4) * 8)) * 2;                                \
    _Pragma("unroll")                                                             \
    for (int pr = 0; pr < 2; pr++) {                                              \
        const int j = lane >> 3;                                                  \
        const int kr = (j & 1) * 8 + (lane & 7);                                  \
        const int ncl = wn * 32 + pr * 16 + (j >> 1) * 8;                         \
        adB[pr] = sB0 + (kr * B_STRIDE + ncl) * 2;                                \
    }                                                                             \
    float acc[4][4][4];                                                           \
    _Pragma("unroll") for (int i = 0; i < 4; i++)                                 \
    _Pragma("unroll") for (int j = 0; j < 4; j++)                                 \
    _Pragma("unroll") for (int q = 0; q < 4; q++) acc[i][j][q] = 0.f;             \
    _Pragma("unroll")                                                             \
    for (int s = 0; s < 4; s++) {       /* prologue: 4 stages in flight */        \
        cp_async16_s(dstA + s * ASTAGE_B, ap + (size_t)s * BK);                   \
        cp_async16_s(dstB + s * BSTAGE_B, bp + (size_t)s * BK * (CWIDTH));        \
        cp_commit();                                                              \
    }                                                                             \
    for (int it = 0; it < (NK); ++it) {                                           \
        cp_wait3();                     /* stage it%NSTG has landed */            \
        __syncthreads();                                                          \
        if (it + 4 < (NK)) {                                                      \
            const int s = (it + 4) % NSTG;                                        \
            cp_async16_s(dstA + s * ASTAGE_B, ap + (size_t)(it + 4) * BK);        \
            cp_async16_s(dstB + s * BSTAGE_B, bp + (size_t)(it + 4) * BK * (CWIDTH)); \
        }                                                                         \
        cp_commit();                                                              \
        const int cur = it % NSTG;                                                \
        const uint32_t oA = cur * ASTAGE_B;                                       \
        const uint32_t oB = cur * BSTAGE_B;                                       \
        uint32_t a[4][4], bb[2][4];                                               \
        _Pragma("unroll")                                                         \
        for (int mt = 0; mt < 4; mt++) ldsm_x4(a[mt], adA[mt] + oA);              \
        _Pragma("unroll")                                                         \
        for (int pr = 0; pr < 2; pr++) ldsm_x4_t(bb[pr], adB[pr] + oB);           \
        _Pragma("unroll")                                                         \
        for (int mt = 0; mt < 4; mt++)                                            \
        _Pragma("unroll")                                                         \
        for (int nt = 0; nt < 4; nt++)                                            \
            mma_f16(acc[mt][nt], a[mt], bb[nt >> 1][(nt & 1) * 2],                \
                    bb[nt >> 1][(nt & 1) * 2 + 1]);                               \
    }

// ---------------- GEMM1: H = fp16(relu(x @ W1 + b1)) ----------------
__global__ __launch_bounds__(256, 2)
void gemm1_tc(const float* __restrict__ b1) {
    const int e   = blockIdx.z;
    const int cnt = g_counts[e];
    const int m0  = blockIdx.y * 128;
    if (m0 >= cnt) return;
    const int off = expert_off(e);
    const int n0  = blockIdx.x * 128;
    const int tid = threadIdx.x;

    const int arow = imin(m0 + (tid >> 1), cnt - 1);
    const __half* ap = g_xh + (size_t)g_row2tok[off + arow] * D_ + (tid & 1) * 8;
    const __half* bp = g_W1h + (size_t)e * D_ * F_ + (size_t)(tid >> 4) * F_ + n0 + (tid & 15) * 8;

    GEMM_CORE(D_ / BK, F_)     // 32 iters

    const float* b1e = b1 + (size_t)e * F_;
#pragma unroll
    for (int mt = 0; mt < 4; ++mt) {
        const int rb = m0 + wm * 64 + mt * 16 + (lane >> 2);
#pragma unroll
        for (int half = 0; half < 2; ++half) {
            const int r = rb + half * 8;
            if (r < cnt) {
                __half* Hrow = g_H + (size_t)(off + r) * F_;
#pragma unroll
                for (int nt = 0; nt < 4; ++nt) {
                    const int c = n0 + wn * 32 + nt * 8 + (lane & 3) * 2;
                    float v0 = fmaxf(acc[mt][nt][half * 2 + 0] + b1e[c],     0.f);
                    float v1 = fmaxf(acc[mt][nt][half * 2 + 1] + b1e[c + 1], 0.f);
                    __half2 h = __floats2half2_rn(v0, v1);
                    *reinterpret_cast<__half2*>(Hrow + c) = h;
                }
            }
        }
    }
}

// ---------------- GEMM2 (split-K=2): g_part[kp] = H @ W2 ----------------
__global__ __launch_bounds__(256, 2)
void gemm2_tc() {
    const int e   = blockIdx.z;
    const int cnt = g_counts[e];
    const int m0  = blockIdx.y * 128;
    if (m0 >= cnt) return;
    const int off = expert_off(e);
    const int kp  = blockIdx.x >> 2;
    const int n0  = (blockIdx.x & 3) * 128;
    const int kbase = kp * (F_ / KSPLIT);
    const int tid = threadIdx.x;

    const int arow = imin(m0 + (tid >> 1), cnt - 1);
    const __half* ap = g_H + (size_t)(off + arow) * F_ + kbase + (tid & 1) * 8;
    const __half* bp = g_W2h + (size_t)e * D_ * F_ + (size_t)(kbase + (tid >> 4)) * D_ + n0 + (tid & 15) * 8;

    GEMM_CORE((F_ / KSPLIT) / BK, D_)    // 64 iters

    float* part = g_part[kp];
#pragma unroll
    for (int mt = 0; mt < 4; ++mt) {
        const int rb = m0 + wm * 64 + mt * 16 + (lane >> 2);
#pragma unroll
        for (int half = 0; half < 2; ++half) {
            const int r = rb + half * 8;
            if (r < cnt) {
                float* prow = part + (size_t)(off + r) * D_;
#pragma unroll
                for (int nt = 0; nt < 4; ++nt) {
                    const int c = n0 + wn * 32 + nt * 8 + (lane & 3) * 2;
                    float2 o;
                    o.x = acc[mt][nt][half * 2 + 0];
                    o.y = acc[mt][nt][half * 2 + 1];
                    *reinterpret_cast<float2*>(prow + c) = o;
                }
            }
        }
    }
}

// ---------------- reduce: out[tok] = part0 + part1 + b2[e] ----------------
__global__ void reduce_kernel(const float* __restrict__ b2,
                              float* __restrict__ out) {
    int idx = blockIdx.x * blockDim.x + threadIdx.x;
    const int rowq = D_ / 4;
    if (idx >= N_ * rowq) return;
    int r  = idx / rowq;
    int c4 = idx - r * rowq;
    int tok = g_row2tok[r];
    int e   = g_rowexpert[r];
    float4 p0 = reinterpret_cast<const float4*>(g_part[0])[(size_t)r * rowq + c4];
    float4 p1 = reinterpret_cast<const float4*>(g_part[1])[(size_t)r * rowq + c4];
    float4 bb = reinterpret_cast<const float4*>(b2 + (size_t)e * D_)[c4];
    float4 o;
    o.x = p0.x + p1.x + bb.x;
    o.y = p0.y + p1.y + bb.y;
    o.z = p0.z + p1.z + bb.z;
    o.w = p0.w + p1.w + bb.w;
    reinterpret_cast<float4*>(out)[(size_t)tok * rowq + c4] = o;
}

// ---------------- launch ----------------
extern "C" void kernel_launch(void* const* d_in, const int* in_sizes, int n_in,
                              void* d_out, int out_size) {
    const float* x  = (const float*)d_in[0];
    const float* Wg = (const float*)d_in[1];
    const float* bg = (const float*)d_in[2];
    const float* W1 = (const float*)d_in[3];
    const float* b1 = (const float*)d_in[4];
    const float* W2 = (const float*)d_in[5];
    const float* b2 = (const float*)d_in[6];
    float* out = (float*)d_out;

    cudaFuncSetAttribute(gemm1_tc, cudaFuncAttributeMaxDynamicSharedMemorySize, SMEM_TOTAL_B);
    cudaFuncSetAttribute(gemm2_tc, cudaFuncAttributeMaxDynamicSharedMemorySize, SMEM_TOTAL_B);

    prep_kernel<<<1184, 256>>>(W1, W2);
    gate_cvt_kernel<<<(N_ * 32) / 256, 256>>>(x, Wg, bg);
    assign_kernel<<<N_ / 256, 256>>>();

    dim3 g1(F_ / 128, N_ / 128, E_);            // (16, 32, 8)
    gemm1_tc<<<g1, 256, SMEM_TOTAL_B>>>(b1);

    dim3 g2((D_ / 128) * KSPLIT, N_ / 128, E_); // (8, 32, 8)
    gemm2_tc<<<g2, 256, SMEM_TOTAL_B>>>();

    reduce_kernel<<<(N_ * D_ / 4) / 256, 256>>>(b2, out);
}

// round 10
// speedup vs baseline: 1.3516x; 1.3516x over previous
#include <cuda_runtime.h>
#include <cuda_fp16.h>
#include <cstdint>

#define E_ 8
#define D_ 512
#define F_ 2048
#define N_ 4096
#define KSPLIT 4

#define BK 16                      // k halves per stage
#define NSTG 3

#define A_ROWS 128
#define A_STRIDE 24                // halves (48B rows, LDSM conflict-free)
#define B_ROWS 16
#define B_STRIDE 136               // halves (272B rows, LDSM conflict-free)

#define WSZ ((size_t)E_ * D_ * F_)
#define XSZ ((size_t)N_ * D_)

#define GATE_BLOCKS 512
#define PREP_BLOCKS 1184

// ---------------- scratch (no allocations allowed) ----------------
__device__ int g_counts[E_];
__device__ int g_expert[N_];
__device__ int g_pos[N_];
__device__ int g_row2tok[N_];
__device__ int g_rowexpert[N_];
__device__ __align__(16) __half g_W1h[WSZ];            // W1 natural [e][d][f], fp16
__device__ __align__(16) __half g_W2h[WSZ];            // W2 natural [e][f][d], fp16
__device__ __align__(16) __half g_xh[XSZ];             // x fp16
__device__ __align__(16) __half g_H[(size_t)N_ * F_];  // hidden fp16
__device__ __align__(16) float  g_part[KSPLIT][(size_t)N_ * D_];

// ---------------- helpers ----------------
__device__ __forceinline__ int imin(int a, int b) { return a < b ? a : b; }

__device__ __forceinline__ void cp_async16_s(uint32_t sm, const void* gm) {
    asm volatile("cp.async.cg.shared.global [%0], [%1], 16;" :: "r"(sm), "l"(gm));
}
__device__ __forceinline__ void cp_commit() { asm volatile("cp.async.commit_group;"); }
__device__ __forceinline__ void cp_wait1()  { asm volatile("cp.async.wait_group 1;"); }

__device__ __forceinline__ void ldsm_x4(uint32_t r[4], uint32_t addr) {
    asm volatile("ldmatrix.sync.aligned.m8n8.x4.shared.b16 {%0,%1,%2,%3}, [%4];"
                 : "=r"(r[0]), "=r"(r[1]), "=r"(r[2]), "=r"(r[3]) : "r"(addr));
}
__device__ __forceinline__ void ldsm_x4_t(uint32_t r[4], uint32_t addr) {
    asm volatile("ldmatrix.sync.aligned.m8n8.x4.trans.shared.b16 {%0,%1,%2,%3}, [%4];"
                 : "=r"(r[0]), "=r"(r[1]), "=r"(r[2]), "=r"(r[3]) : "r"(addr));
}

__device__ __forceinline__ void mma_f16(float c[4], const uint32_t a[4],
                                        uint32_t b0, uint32_t b1) {
    asm volatile(
        "mma.sync.aligned.m16n8k16.row.col.f32.f16.f16.f32 "
        "{%0,%1,%2,%3}, {%4,%5,%6,%7}, {%8,%9}, {%0,%1,%2,%3};"
        : "+f"(c[0]), "+f"(c[1]), "+f"(c[2]), "+f"(c[3])
        : "r"(a[0]), "r"(a[1]), "r"(a[2]), "r"(a[3]), "r"(b0), "r"(b1));
}

__device__ __forceinline__ int expert_off(int e) {
    int s = 0;
#pragma unroll
    for (int i = 0; i < E_; i++) if (i < e) s += g_counts[i];
    return s;
}

// ---------------- fused prep (weights->fp16) + gate + x->fp16 ----------------
// gate blocks [0, GATE_BLOCKS); prep blocks [GATE_BLOCKS, GATE_BLOCKS+PREP_BLOCKS)
// g_counts zeroed by a cudaMemsetAsync before this kernel.
__global__ void prep_gate_kernel(const float* __restrict__ x,
                                 const float* __restrict__ Wg,
                                 const float* __restrict__ bg,
                                 const float* __restrict__ W1,
                                 const float* __restrict__ W2) {
    if (blockIdx.x >= GATE_BLOCKS) {
        // ---- weight fp16 convert (grid-stride over both tensors) ----
        const size_t n1 = WSZ / 4;
        const size_t total = 2 * n1;
        const size_t stride = (size_t)PREP_BLOCKS * blockDim.x;
        for (size_t i = (size_t)(blockIdx.x - GATE_BLOCKS) * blockDim.x + threadIdx.x;
             i < total; i += stride) {
            const float4* src; __half* dst; size_t j;
            if (i < n1) { src = (const float4*)W1; dst = g_W1h; j = i; }
            else        { src = (const float4*)W2; dst = g_W2h; j = i - n1; }
            float4 v = src[j];
            __half2 h0 = __floats2half2_rn(v.x, v.y);
            __half2 h1 = __floats2half2_rn(v.z, v.w);
            reinterpret_cast<uint2*>(dst)[j] = make_uint2(*(uint32_t*)&h0, *(uint32_t*)&h1);
        }
        return;
    }
    // ---- gate + x fp16 convert: one warp per token ----
    int tok  = (blockIdx.x * blockDim.x + threadIdx.x) >> 5;
    int lane = threadIdx.x & 31;
    if (tok >= N_) return;
    const float4* xr = reinterpret_cast<const float4*>(x) + (size_t)tok * (D_ / 4);
    uint2* xo = reinterpret_cast<uint2*>(g_xh) + (size_t)tok * (D_ / 4);

    float acc[E_];
#pragma unroll
    for (int e = 0; e < E_; e++) acc[e] = 0.f;

#pragma unroll
    for (int q = 0; q < 4; q++) {
        int d4 = lane + q * 32;
        float4 v = xr[d4];
        __half2 h0 = __floats2half2_rn(v.x, v.y);
        __half2 h1 = __floats2half2_rn(v.z, v.w);
        xo[d4] = make_uint2(*(uint32_t*)&h0, *(uint32_t*)&h1);
        float vv[4] = {v.x, v.y, v.z, v.w};
#pragma unroll
        for (int t = 0; t < 4; t++) {
            const float4* w = reinterpret_cast<const float4*>(Wg + (size_t)(d4 * 4 + t) * E_);
            float4 w0 = w[0], w1 = w[1];
            acc[0] += vv[t] * w0.x; acc[1] += vv[t] * w0.y;
            acc[2] += vv[t] * w0.z; acc[3] += vv[t] * w0.w;
            acc[4] += vv[t] * w1.x; acc[5] += vv[t] * w1.y;
            acc[6] += vv[t] * w1.z; acc[7] += vv[t] * w1.w;
        }
    }
#pragma unroll
    for (int off = 16; off > 0; off >>= 1)
#pragma unroll
        for (int e = 0; e < E_; e++)
            acc[e] += __shfl_down_sync(0xFFFFFFFFu, acc[e], off);
    if (lane == 0) {
        float best = acc[0] + bg[0];
        int bi = 0;
#pragma unroll
        for (int e = 1; e < E_; e++) {
            float v = acc[e] + bg[e];
            if (v > best) { best = v; bi = e; }
        }
        int p = atomicAdd(&g_counts[bi], 1);
        g_expert[tok] = bi;
        g_pos[tok]    = p;
    }
}

// ---------------- assign compacted rows ----------------
__global__ void assign_kernel() {
    int t = blockIdx.x * blockDim.x + threadIdx.x;
    if (t >= N_) return;
    int e = g_expert[t];
    int r = expert_off(e) + g_pos[t];
    g_row2tok[r]   = t;
    g_rowexpert[r] = e;
}

// =====================================================================
// fp16 GEMM core (round-8 proven config): 256 thr, 8 warps (2x4),
// warp tile 64x32 = 4x4 m16n8k16. Static smem, 3-stage cp.async ring,
// wait_group 1, one __syncthreads per iter. CWIDTH = B gmem row width.
// =====================================================================
#define GEMM_CORE(NK, CWIDTH)                                                     \
    __shared__ __align__(16) __half smA[NSTG][A_ROWS * A_STRIDE];                 \
    __shared__ __align__(16) __half smB[NSTG][B_ROWS * B_STRIDE];                 \
    const int lane = tid & 31;                                                    \
    const int warp = tid >> 5;                                                    \
    const int wm   = warp >> 2;        /* 0..1 */                                 \
    const int wn   = warp & 3;         /* 0..3 */                                 \
    const uint32_t sA0 = (uint32_t)__cvta_generic_to_shared(&smA[0][0]);          \
    const uint32_t sB0 = (uint32_t)__cvta_generic_to_shared(&smB[0][0]);          \
    const int la_row = tid >> 1;                                                  \
    const int la_kc  = (tid & 1) * 8;                                             \
    const int lb_k   = tid >> 4;                                                  \
    const int lb_nc  = (tid & 15) * 8;                                            \
    const uint32_t dstA = sA0 + (la_row * A_STRIDE + la_kc) * 2;                  \
    const uint32_t dstB = sB0 + (lb_k * B_STRIDE + lb_nc) * 2;                    \
    uint32_t adA[4], adB[2];                                                      \
    _Pragma("unroll")                                                             \
    for (int mt = 0; mt < 4; mt++)                                                \
        adA[mt] = sA0 + (((wm * 64 + mt * 16 + (lane & 15)) * A_STRIDE            \
                          + (lane >> 4) * 8)) * 2;                                \
    _Pragma("unroll")                                                             \
    for (int pr = 0; pr < 2; pr++) {                                              \
        const int j = lane >> 3;                                                  \
        const int kr = (j & 1) * 8 + (lane & 7);                                  \
        const int ncl = wn * 32 + pr * 16 + (j >> 1) * 8;                         \
        adB[pr] = sB0 + (kr * B_STRIDE + ncl) * 2;                                \
    }                                                                             \
    float acc[4][4][4];                                                           \
    _Pragma("unroll") for (int i = 0; i < 4; i++)                                 \
    _Pragma("unroll") for (int j = 0; j < 4; j++)                                 \
    _Pragma("unroll") for (int q = 0; q < 4; q++) acc[i][j][q] = 0.f;             \
    _Pragma("unroll")                                                             \
    for (int s = 0; s < 2; s++) {                                                 \
        cp_async16_s(dstA + s * (A_ROWS * A_STRIDE * 2), ap + (size_t)s * BK);    \
        cp_async16_s(dstB + s * (B_ROWS * B_STRIDE * 2), bp + (size_t)s * BK * (CWIDTH)); \
        cp_commit();                                                              \
    }                                                                             \
    for (int it = 0; it < (NK); ++it) {                                           \
        cp_wait1();                                                               \
        __syncthreads();                                                          \
        if (it + 2 < (NK)) {                                                      \
            const int s = (it + 2) % NSTG;                                        \
            cp_async16_s(dstA + s * (A_ROWS * A_STRIDE * 2), ap + (size_t)(it + 2) * BK); \
            cp_async16_s(dstB + s * (B_ROWS * B_STRIDE * 2), bp + (size_t)(it + 2) * BK * (CWIDTH)); \
        }                                                                         \
        cp_commit();                                                              \
        const int cur = it % NSTG;                                                \
        const uint32_t oA = cur * (A_ROWS * A_STRIDE * 2);                        \
        const uint32_t oB = cur * (B_ROWS * B_STRIDE * 2);                        \
        uint32_t a[4][4], bb[2][4];                                               \
        _Pragma("unroll")                                                         \
        for (int mt = 0; mt < 4; mt++) ldsm_x4(a[mt], adA[mt] + oA);              \
        _Pragma("unroll")                                                         \
        for (int pr = 0; pr < 2; pr++) ldsm_x4_t(bb[pr], adB[pr] + oB);           \
        _Pragma("unroll")                                                         \
        for (int mt = 0; mt < 4; mt++)                                            \
        _Pragma("unroll")                                                         \
        for (int nt = 0; nt < 4; nt++)                                            \
            mma_f16(acc[mt][nt], a[mt], bb[nt >> 1][(nt & 1) * 2],                \
                    bb[nt >> 1][(nt & 1) * 2 + 1]);                               \
    }

// ---------------- GEMM1: H = fp16(relu(x @ W1 + b1)) ----------------
__global__ __launch_bounds__(256, 2)
void gemm1_tc(const float* __restrict__ b1) {
    const int e   = blockIdx.z;
    const int cnt = g_counts[e];
    const int m0  = blockIdx.y * 128;
    if (m0 >= cnt) return;
    const int off = expert_off(e);
    const int n0  = blockIdx.x * 128;
    const int tid = threadIdx.x;

    const int arow = imin(m0 + (tid >> 1), cnt - 1);
    const __half* ap = g_xh + (size_t)g_row2tok[off + arow] * D_ + (tid & 1) * 8;
    const __half* bp = g_W1h + (size_t)e * D_ * F_ + (size_t)(tid >> 4) * F_ + n0 + (tid & 15) * 8;

    GEMM_CORE(D_ / BK, F_)     // 32 iters

    const float* b1e = b1 + (size_t)e * F_;
#pragma unroll
    for (int mt = 0; mt < 4; ++mt) {
        const int rb = m0 + wm * 64 + mt * 16 + (lane >> 2);
#pragma unroll
        for (int half = 0; half < 2; ++half) {
            const int r = rb + half * 8;
            if (r < cnt) {
                __half* Hrow = g_H + (size_t)(off + r) * F_;
#pragma unroll
                for (int nt = 0; nt < 4; ++nt) {
                    const int c = n0 + wn * 32 + nt * 8 + (lane & 3) * 2;
                    float v0 = fmaxf(acc[mt][nt][half * 2 + 0] + b1e[c],     0.f);
                    float v1 = fmaxf(acc[mt][nt][half * 2 + 1] + b1e[c + 1], 0.f);
                    __half2 h = __floats2half2_rn(v0, v1);
                    *reinterpret_cast<__half2*>(Hrow + c) = h;
                }
            }
        }
    }
}

// ---------------- GEMM2 (split-K=4): g_part[kp] = H @ W2 ----------------
__global__ __launch_bounds__(256, 2)
void gemm2_tc() {
    const int e   = blockIdx.z;
    const int cnt = g_counts[e];
    const int m0  = blockIdx.y * 128;
    if (m0 >= cnt) return;
    const int off = expert_off(e);
    const int kp  = blockIdx.x >> 2;             // 0..3
    const int n0  = (blockIdx.x & 3) * 128;
    const int kbase = kp * (F_ / KSPLIT);        // 512 per split
    const int tid = threadIdx.x;

    const int arow = imin(m0 + (tid >> 1), cnt - 1);
    const __half* ap = g_H + (size_t)(off + arow) * F_ + kbase + (tid & 1) * 8;
    const __half* bp = g_W2h + (size_t)e * D_ * F_ + (size_t)(kbase + (tid >> 4)) * D_ + n0 + (tid & 15) * 8;

    GEMM_CORE((F_ / KSPLIT) / BK, D_)    // 32 iters

    float* part = g_part[kp];
#pragma unroll
    for (int mt = 0; mt < 4; ++mt) {
        const int rb = m0 + wm * 64 + mt * 16 + (lane >> 2);
#pragma unroll
        for (int half = 0; half < 2; ++half) {
            const int r = rb + half * 8;
            if (r < cnt) {
                float* prow = part + (size_t)(off + r) * D_;
#pragma unroll
                for (int nt = 0; nt < 4; ++nt) {
                    const int c = n0 + wn * 32 + nt * 8 + (lane & 3) * 2;
                    float2 o;
                    o.x = acc[mt][nt][half * 2 + 0];
                    o.y = acc[mt][nt][half * 2 + 1];
                    *reinterpret_cast<float2*>(prow + c) = o;
                }
            }
        }
    }
}

// ---------------- reduce: out[tok] = sum_kp part[kp] + b2[e] ----------------
__global__ void reduce_kernel(const float* __restrict__ b2,
                              float* __restrict__ out) {
    int idx = blockIdx.x * blockDim.x + threadIdx.x;
    const int rowq = D_ / 4;
    if (idx >= N_ * rowq) return;
    int r  = idx / rowq;
    int c4 = idx - r * rowq;
    int tok = g_row2tok[r];
    int e   = g_rowexpert[r];
    float4 bb = reinterpret_cast<const float4*>(b2 + (size_t)e * D_)[c4];
    float4 o = bb;
#pragma unroll
    for (int kp = 0; kp < KSPLIT; kp++) {
        float4 p = reinterpret_cast<const float4*>(g_part[kp])[(size_t)r * rowq + c4];
        o.x += p.x; o.y += p.y; o.z += p.z; o.w += p.w;
    }
    reinterpret_cast<float4*>(out)[(size_t)tok * rowq + c4] = o;
}

// ---------------- launch ----------------
extern "C" void kernel_launch(void* const* d_in, const int* in_sizes, int n_in,
                              void* d_out, int out_size) {
    const float* x  = (const float*)d_in[0];
    const float* Wg = (const float*)d_in[1];
    const float* bg = (const float*)d_in[2];
    const float* W1 = (const float*)d_in[3];
    const float* b1 = (const float*)d_in[4];
    const float* W2 = (const float*)d_in[5];
    const float* b2 = (const float*)d_in[6];
    float* out = (float*)d_out;

    // zero routing counts (graph-capturable memset node, no allocation)
    void* counts_addr = nullptr;
    cudaGetSymbolAddress(&counts_addr, g_counts);
    cudaMemsetAsync(counts_addr, 0, E_ * sizeof(int));

    prep_gate_kernel<<<GATE_BLOCKS + PREP_BLOCKS, 256>>>(x, Wg, bg, W1, W2);
    assign_kernel<<<N_ / 256, 256>>>();

    dim3 g1(F_ / 128, N_ / 128, E_);            // (16, 32, 8)
    gemm1_tc<<<g1, 256>>>(b1);

    dim3 g2((D_ / 128) * KSPLIT, N_ / 128, E_); // (16, 32, 8)
    gemm2_tc<<<g2, 256>>>();

    reduce_kernel<<<(N_ * D_ / 4) / 256, 256>>>(b2, out);
}

// round 11
// speedup vs baseline: 1.3859x; 1.0254x over previous
#include <cuda_runtime.h>
#include <cuda_fp16.h>
#include <cstdint>

#define E_ 8
#define D_ 512
#define F_ 2048
#define N_ 4096
#define KSPLIT 2

#define BK 16                      // k halves per stage
#define NSTG 3

#define A_ROWS 128
#define A_STRIDE 24                // halves (48B rows, LDSM conflict-free)
#define B_ROWS 16
#define B_STRIDE 136               // halves (272B rows, LDSM conflict-free)

#define WSZ ((size_t)E_ * D_ * F_)
#define XSZ ((size_t)N_ * D_)

#define GATE_BLOCKS 512
#define PREP_BLOCKS 1184

#define NTILE2 4                   // gemm2 n-tiles
#define NFLAGS (E_ * (N_ / 128) * NTILE2)   // 1024 tile flags

// ---------------- scratch (no allocations allowed) ----------------
__device__ int g_counts[E_];
__device__ int g_flags[NFLAGS];
__device__ int g_expert[N_];
__device__ int g_pos[N_];
__device__ int g_row2tok[N_];
__device__ __align__(16) __half g_W1h[WSZ];            // W1 natural [e][d][f], fp16
__device__ __align__(16) __half g_W2h[WSZ];            // W2 natural [e][f][d], fp16
__device__ __align__(16) __half g_xh[XSZ];             // x fp16
__device__ __align__(16) __half g_H[(size_t)N_ * F_];  // hidden fp16
__device__ __align__(16) float  g_part[KSPLIT][(size_t)N_ * D_];

// ---------------- helpers ----------------
__device__ __forceinline__ int imin(int a, int b) { return a < b ? a : b; }

__device__ __forceinline__ void cp_async16_s(uint32_t sm, const void* gm) {
    asm volatile("cp.async.cg.shared.global [%0], [%1], 16;" :: "r"(sm), "l"(gm));
}
__device__ __forceinline__ void cp_commit() { asm volatile("cp.async.commit_group;"); }
__device__ __forceinline__ void cp_wait1()  { asm volatile("cp.async.wait_group 1;"); }

__device__ __forceinline__ void ldsm_x4(uint32_t r[4], uint32_t addr) {
    asm volatile("ldmatrix.sync.aligned.m8n8.x4.shared.b16 {%0,%1,%2,%3}, [%4];"
                 : "=r"(r[0]), "=r"(r[1]), "=r"(r[2]), "=r"(r[3]) : "r"(addr));
}
__device__ __forceinline__ void ldsm_x4_t(uint32_t r[4], uint32_t addr) {
    asm volatile("ldmatrix.sync.aligned.m8n8.x4.trans.shared.b16 {%0,%1,%2,%3}, [%4];"
                 : "=r"(r[0]), "=r"(r[1]), "=r"(r[2]), "=r"(r[3]) : "r"(addr));
}

__device__ __forceinline__ void mma_f16(float c[4], const uint32_t a[4],
                                        uint32_t b0, uint32_t b1) {
    asm volatile(
        "mma.sync.aligned.m16n8k16.row.col.f32.f16.f16.f32 "
        "{%0,%1,%2,%3}, {%4,%5,%6,%7}, {%8,%9}, {%0,%1,%2,%3};"
        : "+f"(c[0]), "+f"(c[1]), "+f"(c[2]), "+f"(c[3])
        : "r"(a[0]), "r"(a[1]), "r"(a[2]), "r"(a[3]), "r"(b0), "r"(b1));
}

__device__ __forceinline__ int expert_off(int e) {
    int s = 0;
#pragma unroll
    for (int i = 0; i < E_; i++) if (i < e) s += g_counts[i];
    return s;
}

// ---------------- fused prep (weights->fp16) + gate + x->fp16 ----------------
// gate blocks [0, GATE_BLOCKS); prep blocks [GATE_BLOCKS, GATE_BLOCKS+PREP_BLOCKS)
// g_counts zeroed by cudaMemsetAsync before this kernel.
__global__ void prep_gate_kernel(const float* __restrict__ x,
                                 const float* __restrict__ Wg,
                                 const float* __restrict__ bg,
                                 const float* __restrict__ W1,
                                 const float* __restrict__ W2) {
    if (blockIdx.x >= GATE_BLOCKS) {
        const size_t n1 = WSZ / 4;
        const size_t total = 2 * n1;
        const size_t stride = (size_t)PREP_BLOCKS * blockDim.x;
        for (size_t i = (size_t)(blockIdx.x - GATE_BLOCKS) * blockDim.x + threadIdx.x;
             i < total; i += stride) {
            const float4* src; __half* dst; size_t j;
            if (i < n1) { src = (const float4*)W1; dst = g_W1h; j = i; }
            else        { src = (const float4*)W2; dst = g_W2h; j = i - n1; }
            float4 v = src[j];
            __half2 h0 = __floats2half2_rn(v.x, v.y);
            __half2 h1 = __floats2half2_rn(v.z, v.w);
            reinterpret_cast<uint2*>(dst)[j] = make_uint2(*(uint32_t*)&h0, *(uint32_t*)&h1);
        }
        return;
    }
    // ---- gate + x fp16 convert: one warp per token ----
    int tok  = (blockIdx.x * blockDim.x + threadIdx.x) >> 5;
    int lane = threadIdx.x & 31;
    if (tok >= N_) return;
    const float4* xr = reinterpret_cast<const float4*>(x) + (size_t)tok * (D_ / 4);
    uint2* xo = reinterpret_cast<uint2*>(g_xh) + (size_t)tok * (D_ / 4);

    float acc[E_];
#pragma unroll
    for (int e = 0; e < E_; e++) acc[e] = 0.f;

#pragma unroll
    for (int q = 0; q < 4; q++) {
        int d4 = lane + q * 32;
        float4 v = xr[d4];
        __half2 h0 = __floats2half2_rn(v.x, v.y);
        __half2 h1 = __floats2half2_rn(v.z, v.w);
        xo[d4] = make_uint2(*(uint32_t*)&h0, *(uint32_t*)&h1);
        float vv[4] = {v.x, v.y, v.z, v.w};
#pragma unroll
        for (int t = 0; t < 4; t++) {
            const float4* w = reinterpret_cast<const float4*>(Wg + (size_t)(d4 * 4 + t) * E_);
            float4 w0 = w[0], w1 = w[1];
            acc[0] += vv[t] * w0.x; acc[1] += vv[t] * w0.y;
            acc[2] += vv[t] * w0.z; acc[3] += vv[t] * w0.w;
            acc[4] += vv[t] * w1.x; acc[5] += vv[t] * w1.y;
            acc[6] += vv[t] * w1.z; acc[7] += vv[t] * w1.w;
        }
    }
#pragma unroll
    for (int off = 16; off > 0; off >>= 1)
#pragma unroll
        for (int e = 0; e < E_; e++)
            acc[e] += __shfl_down_sync(0xFFFFFFFFu, acc[e], off);
    if (lane == 0) {
        float best = acc[0] + bg[0];
        int bi = 0;
#pragma unroll
        for (int e = 1; e < E_; e++) {
            float v = acc[e] + bg[e];
            if (v > best) { best = v; bi = e; }
        }
        int p = atomicAdd(&g_counts[bi], 1);
        g_expert[tok] = bi;
        g_pos[tok]    = p;
    }
}

// ---------------- assign compacted rows ----------------
__global__ void assign_kernel() {
    int t = blockIdx.x * blockDim.x + threadIdx.x;
    if (t >= N_) return;
    int e = g_expert[t];
    int r = expert_off(e) + g_pos[t];
    g_row2tok[r] = t;
}

// =====================================================================
// fp16 GEMM core (round-8 proven config): 256 thr, 8 warps (2x4),
// warp tile 64x32 = 4x4 m16n8k16. Static smem, 3-stage cp.async ring,
// wait_group 1, one __syncthreads per iter. CWIDTH = B gmem row width.
// =====================================================================
#define GEMM_CORE(NK, CWIDTH)                                                     \
    __shared__ __align__(16) __half smA[NSTG][A_ROWS * A_STRIDE];                 \
    __shared__ __align__(16) __half smB[NSTG][B_ROWS * B_STRIDE];                 \
    const int lane = tid & 31;                                                    \
    const int warp = tid >> 5;                                                    \
    const int wm   = warp >> 2;        /* 0..1 */                                 \
    const int wn   = warp & 3;         /* 0..3 */                                 \
    const uint32_t sA0 = (uint32_t)__cvta_generic_to_shared(&smA[0][0]);          \
    const uint32_t sB0 = (uint32_t)__cvta_generic_to_shared(&smB[0][0]);          \
    const int la_row = tid >> 1;                                                  \
    const int la_kc  = (tid & 1) * 8;                                             \
    const int lb_k   = tid >> 4;                                                  \
    const int lb_nc  = (tid & 15) * 8;                                            \
    const uint32_t dstA = sA0 + (la_row * A_STRIDE + la_kc) * 2;                  \
    const uint32_t dstB = sB0 + (lb_k * B_STRIDE + lb_nc) * 2;                    \
    uint32_t adA[4], adB[2];                                                      \
    _Pragma("unroll")                                                             \
    for (int mt = 0; mt < 4; mt++)                                                \
        adA[mt] = sA0 + (((wm * 64 + mt * 16 + (lane & 15)) * A_STRIDE            \
                          + (lane >> 4) * 8)) * 2;                                \
    _Pragma("unroll")                                                             \
    for (int pr = 0; pr < 2; pr++) {                                              \
        const int j = lane >> 3;                                                  \
        const int kr = (j & 1) * 8 + (lane & 7);                                  \
        const int ncl = wn * 32 + pr * 16 + (j >> 1) * 8;                         \
        adB[pr] = sB0 + (kr * B_STRIDE + ncl) * 2;                                \
    }                                                                             \
    float acc[4][4][4];                                                           \
    _Pragma("unroll") for (int i = 0; i < 4; i++)                                 \
    _Pragma("unroll") for (int j = 0; j < 4; j++)                                 \
    _Pragma("unroll") for (int q = 0; q < 4; q++) acc[i][j][q] = 0.f;             \
    _Pragma("unroll")                                                             \
    for (int s = 0; s < 2; s++) {                                                 \
        cp_async16_s(dstA + s * (A_ROWS * A_STRIDE * 2), ap + (size_t)s * BK);    \
        cp_async16_s(dstB + s * (B_ROWS * B_STRIDE * 2), bp + (size_t)s * BK * (CWIDTH)); \
        cp_commit();                                                              \
    }                                                                             \
    for (int it = 0; it < (NK); ++it) {                                           \
        cp_wait1();                                                               \
        __syncthreads();                                                          \
        if (it + 2 < (NK)) {                                                      \
            const int s = (it + 2) % NSTG;                                        \
            cp_async16_s(dstA + s * (A_ROWS * A_STRIDE * 2), ap + (size_t)(it + 2) * BK); \
            cp_async16_s(dstB + s * (B_ROWS * B_STRIDE * 2), bp + (size_t)(it + 2) * BK * (CWIDTH)); \
        }                                                                         \
        cp_commit();                                                              \
        const int cur = it % NSTG;                                                \
        const uint32_t oA = cur * (A_ROWS * A_STRIDE * 2);                        \
        const uint32_t oB = cur * (B_ROWS * B_STRIDE * 2);                        \
        uint32_t a[4][4], bb[2][4];                                               \
        _Pragma("unroll")                                                         \
        for (int mt = 0; mt < 4; mt++) ldsm_x4(a[mt], adA[mt] + oA);              \
        _Pragma("unroll")                                                         \
        for (int pr = 0; pr < 2; pr++) ldsm_x4_t(bb[pr], adB[pr] + oB);           \
        _Pragma("unroll")                                                         \
        for (int mt = 0; mt < 4; mt++)                                            \
        _Pragma("unroll")                                                         \
        for (int nt = 0; nt < 4; nt++)                                            \
            mma_f16(acc[mt][nt], a[mt], bb[nt >> 1][(nt & 1) * 2],                \
                    bb[nt >> 1][(nt & 1) * 2 + 1]);                               \
    }

// ---------------- GEMM1: H = fp16(relu(x @ W1 + b1)) ----------------
__global__ __launch_bounds__(256, 2)
void gemm1_tc(const float* __restrict__ b1) {
    const int e   = blockIdx.z;
    const int cnt = g_counts[e];
    const int m0  = blockIdx.y * 128;
    if (m0 >= cnt) return;
    const int off = expert_off(e);
    const int n0  = blockIdx.x * 128;
    const int tid = threadIdx.x;

    const int arow = imin(m0 + (tid >> 1), cnt - 1);
    const __half* ap = g_xh + (size_t)g_row2tok[off + arow] * D_ + (tid & 1) * 8;
    const __half* bp = g_W1h + (size_t)e * D_ * F_ + (size_t)(tid >> 4) * F_ + n0 + (tid & 15) * 8;

    GEMM_CORE(D_ / BK, F_)     // 32 iters

    const float* b1e = b1 + (size_t)e * F_;
#pragma unroll
    for (int mt = 0; mt < 4; ++mt) {
        const int rb = m0 + wm * 64 + mt * 16 + (lane >> 2);
#pragma unroll
        for (int half = 0; half < 2; ++half) {
            const int r = rb + half * 8;
            if (r < cnt) {
                __half* Hrow = g_H + (size_t)(off + r) * F_;
#pragma unroll
                for (int nt = 0; nt < 4; ++nt) {
                    const int c = n0 + wn * 32 + nt * 8 + (lane & 3) * 2;
                    float v0 = fmaxf(acc[mt][nt][half * 2 + 0] + b1e[c],     0.f);
                    float v1 = fmaxf(acc[mt][nt][half * 2 + 1] + b1e[c + 1], 0.f);
                    __half2 h = __floats2half2_rn(v0, v1);
                    *reinterpret_cast<__half2*>(Hrow + c) = h;
                }
            }
        }
    }
}

// ---------------- GEMM2 (split-K=2, fused reduce): out = H @ W2 + b2 ----------
// Each (m,n,e) tile has 2 partner CTAs (kp=0,1). Both write their partial to
// g_part[kp]; the SECOND finisher (per-tile flag) reads the partner's partial
// and writes out = (partner + mine) + b2 directly. Commutative add -> the
// result is bit-identical regardless of which CTA wins. Flags zeroed per launch.
__global__ __launch_bounds__(256, 2)
void gemm2_tc(const float* __restrict__ b2, float* __restrict__ out) {
    const int e   = blockIdx.z;
    const int cnt = g_counts[e];
    const int m0  = blockIdx.y * 128;
    if (m0 >= cnt) return;
    const int off = expert_off(e);
    const int kp  = blockIdx.x >> 2;             // 0..1
    const int ni  = blockIdx.x & 3;
    const int n0  = ni * 128;
    const int kbase = kp * (F_ / KSPLIT);        // 1024 per split
    const int tid = threadIdx.x;
    const int tileid = (e * (N_ / 128) + blockIdx.y) * NTILE2 + ni;

    const int arow = imin(m0 + (tid >> 1), cnt - 1);
    const __half* ap = g_H + (size_t)(off + arow) * F_ + kbase + (tid & 1) * 8;
    const __half* bp = g_W2h + (size_t)e * D_ * F_ + (size_t)(kbase + (tid >> 4)) * D_ + n0 + (tid & 15) * 8;

    GEMM_CORE((F_ / KSPLIT) / BK, D_)    // 64 iters

    // 1) stage my partial
    float* part = g_part[kp];
#pragma unroll
    for (int mt = 0; mt < 4; ++mt) {
        const int rb = m0 + wm * 64 + mt * 16 + (lane >> 2);
#pragma unroll
        for (int half = 0; half < 2; ++half) {
            const int r = rb + half * 8;
            if (r < cnt) {
                float* prow = part + (size_t)(off + r) * D_;
#pragma unroll
                for (int nt = 0; nt < 4; ++nt) {
                    const int c = n0 + wn * 32 + nt * 8 + (lane & 3) * 2;
                    float2 o;
                    o.x = acc[mt][nt][half * 2 + 0];
                    o.y = acc[mt][nt][half * 2 + 1];
                    *reinterpret_cast<float2*>(prow + c) = o;
                }
            }
        }
    }

    // 2) handshake: second finisher combines
    __threadfence();
    __syncthreads();
    __shared__ int s_old;
    if (tid == 0) s_old = atomicAdd(&g_flags[tileid], 1);
    __syncthreads();
    if (s_old != 1) return;          // first finisher done
    __threadfence();                 // acquire partner's partial

    const float* other = g_part[1 - kp];
    const float* b2e = b2 + (size_t)e * D_;
#pragma unroll
    for (int mt = 0; mt < 4; ++mt) {
        const int rb = m0 + wm * 64 + mt * 16 + (lane >> 2);
#pragma unroll
        for (int half = 0; half < 2; ++half) {
            const int r = rb + half * 8;
            if (r < cnt) {
                const int tok = g_row2tok[off + r];
                const float* orow = other + (size_t)(off + r) * D_;
                float* dst = out + (size_t)tok * D_;
#pragma unroll
                for (int nt = 0; nt < 4; ++nt) {
                    const int c = n0 + wn * 32 + nt * 8 + (lane & 3) * 2;
                    float2 p = *reinterpret_cast<const float2*>(orow + c);
                    float2 o;
                    o.x = (p.x + acc[mt][nt][half * 2 + 0]) + b2e[c];
                    o.y = (p.y + acc[mt][nt][half * 2 + 1]) + b2e[c + 1];
                    *reinterpret_cast<float2*>(dst + c) = o;
                }
            }
        }
    }
}

// ---------------- launch ----------------
extern "C" void kernel_launch(void* const* d_in, const int* in_sizes, int n_in,
                              void* d_out, int out_size) {
    const float* x  = (const float*)d_in[0];
    const float* Wg = (const float*)d_in[1];
    const float* bg = (const float*)d_in[2];
    const float* W1 = (const float*)d_in[3];
    const float* b1 = (const float*)d_in[4];
    const float* W2 = (const float*)d_in[5];
    const float* b2 = (const float*)d_in[6];
    float* out = (float*)d_out;

    // zero routing counts + tile flags (graph-capturable memset nodes)
    void* counts_addr = nullptr;
    cudaGetSymbolAddress(&counts_addr, g_counts);
    cudaMemsetAsync(counts_addr, 0, E_ * sizeof(int));
    void* flags_addr = nullptr;
    cudaGetSymbolAddress(&flags_addr, g_flags);
    cudaMemsetAsync(flags_addr, 0, NFLAGS * sizeof(int));

    prep_gate_kernel<<<GATE_BLOCKS + PREP_BLOCKS, 256>>>(x, Wg, bg, W1, W2);
    assign_kernel<<<N_ / 256, 256>>>();

    dim3 g1(F_ / 128, N_ / 128, E_);            // (16, 32, 8)
    gemm1_tc<<<g1, 256>>>(b1);

    dim3 g2(NTILE2 * KSPLIT, N_ / 128, E_);     // (8, 32, 8)
    gemm2_tc<<<g2, 256>>>(b2, out);
}

// round 12
// speedup vs baseline: 1.4577x; 1.0518x over previous
#include <cuda_runtime.h>
#include <cuda_fp16.h>
#include <cstdint>

#define E_ 8
#define D_ 512
#define F_ 2048
#define N_ 4096
#define KSPLIT 2

#define BK 32                      // k halves per stage (2 x k16 sub-blocks)
#define NSTG 3

#define A_STRIDE 40                // halves; 20-word rows, LDSM conflict-free
#define B_STRIDE 136               // halves; unchanged, LDSM conflict-free

#define ASTG_B (128 * A_STRIDE * 2)     // 10240 B per A stage
#define BSTG_B (32 * B_STRIDE * 2)      // 8704 B per B stage
#define BBASE_B (NSTG * ASTG_B)         // 30720
#define SMEM_B (BBASE_B + NSTG * BSTG_B)  // 56832

#define WSZ ((size_t)E_ * D_ * F_)
#define XSZ ((size_t)N_ * D_)

#define GATE_BLOCKS 512
#define PREP_BLOCKS 1184

#define NTILE2 4
#define NFLAGS (E_ * (N_ / 128) * NTILE2)

// ---------------- scratch (no allocations allowed) ----------------
__device__ int g_counts[E_];
__device__ int g_flags[NFLAGS];
__device__ int g_expert[N_];
__device__ int g_pos[N_];
__device__ int g_row2tok[N_];
__device__ __align__(16) __half g_W1h[WSZ];            // W1 natural [e][d][f], fp16
__device__ __align__(16) __half g_W2h[WSZ];            // W2 natural [e][f][d], fp16
__device__ __align__(16) __half g_xh[XSZ];             // x fp16
__device__ __align__(16) __half g_H[(size_t)N_ * F_];  // hidden fp16
__device__ __align__(16) float  g_part[KSPLIT][(size_t)N_ * D_];

// ---------------- helpers ----------------
__device__ __forceinline__ int imin(int a, int b) { return a < b ? a : b; }

__device__ __forceinline__ void cp_async16_s(uint32_t sm, const void* gm) {
    asm volatile("cp.async.cg.shared.global [%0], [%1], 16;" :: "r"(sm), "l"(gm));
}
__device__ __forceinline__ void cp_commit() { asm volatile("cp.async.commit_group;"); }
__device__ __forceinline__ void cp_wait1()  { asm volatile("cp.async.wait_group 1;"); }

__device__ __forceinline__ void ldsm_x4(uint32_t r[4], uint32_t addr) {
    asm volatile("ldmatrix.sync.aligned.m8n8.x4.shared.b16 {%0,%1,%2,%3}, [%4];"
                 : "=r"(r[0]), "=r"(r[1]), "=r"(r[2]), "=r"(r[3]) : "r"(addr));
}
__device__ __forceinline__ void ldsm_x4_t(uint32_t r[4], uint32_t addr) {
    asm volatile("ldmatrix.sync.aligned.m8n8.x4.trans.shared.b16 {%0,%1,%2,%3}, [%4];"
                 : "=r"(r[0]), "=r"(r[1]), "=r"(r[2]), "=r"(r[3]) : "r"(addr));
}

__device__ __forceinline__ void mma_f16(float c[4], const uint32_t a[4],
                                        uint32_t b0, uint32_t b1) {
    asm volatile(
        "mma.sync.aligned.m16n8k16.row.col.f32.f16.f16.f32 "
        "{%0,%1,%2,%3}, {%4,%5,%6,%7}, {%8,%9}, {%0,%1,%2,%3};"
        : "+f"(c[0]), "+f"(c[1]), "+f"(c[2]), "+f"(c[3])
        : "r"(a[0]), "r"(a[1]), "r"(a[2]), "r"(a[3]), "r"(b0), "r"(b1));
}

__device__ __forceinline__ int expert_off(int e) {
    int s = 0;
#pragma unroll
    for (int i = 0; i < E_; i++) if (i < e) s += g_counts[i];
    return s;
}

// ---------------- fused prep (weights->fp16) + gate + x->fp16 ----------------
__global__ void prep_gate_kernel(const float* __restrict__ x,
                                 const float* __restrict__ Wg,
                                 const float* __restrict__ bg,
                                 const float* __restrict__ W1,
                                 const float* __restrict__ W2) {
    if (blockIdx.x >= GATE_BLOCKS) {
        const size_t n1 = WSZ / 4;
        const size_t total = 2 * n1;
        const size_t stride = (size_t)PREP_BLOCKS * blockDim.x;
        for (size_t i = (size_t)(blockIdx.x - GATE_BLOCKS) * blockDim.x + threadIdx.x;
             i < total; i += stride) {
            const float4* src; __half* dst; size_t j;
            if (i < n1) { src = (const float4*)W1; dst = g_W1h; j = i; }
            else        { src = (const float4*)W2; dst = g_W2h; j = i - n1; }
            float4 v = src[j];
            __half2 h0 = __floats2half2_rn(v.x, v.y);
            __half2 h1 = __floats2half2_rn(v.z, v.w);
            reinterpret_cast<uint2*>(dst)[j] = make_uint2(*(uint32_t*)&h0, *(uint32_t*)&h1);
        }
        return;
    }
    int tok  = (blockIdx.x * blockDim.x + threadIdx.x) >> 5;
    int lane = threadIdx.x & 31;
    if (tok >= N_) return;
    const float4* xr = reinterpret_cast<const float4*>(x) + (size_t)tok * (D_ / 4);
    uint2* xo = reinterpret_cast<uint2*>(g_xh) + (size_t)tok * (D_ / 4);

    float acc[E_];
#pragma unroll
    for (int e = 0; e < E_; e++) acc[e] = 0.f;

#pragma unroll
    for (int q = 0; q < 4; q++) {
        int d4 = lane + q * 32;
        float4 v = xr[d4];
        __half2 h0 = __floats2half2_rn(v.x, v.y);
        __half2 h1 = __floats2half2_rn(v.z, v.w);
        xo[d4] = make_uint2(*(uint32_t*)&h0, *(uint32_t*)&h1);
        float vv[4] = {v.x, v.y, v.z, v.w};
#pragma unroll
        for (int t = 0; t < 4; t++) {
            const float4* w = reinterpret_cast<const float4*>(Wg + (size_t)(d4 * 4 + t) * E_);
            float4 w0 = w[0], w1 = w[1];
            acc[0] += vv[t] * w0.x; acc[1] += vv[t] * w0.y;
            acc[2] += vv[t] * w0.z; acc[3] += vv[t] * w0.w;
            acc[4] += vv[t] * w1.x; acc[5] += vv[t] * w1.y;
            acc[6] += vv[t] * w1.z; acc[7] += vv[t] * w1.w;
        }
    }
#pragma unroll
    for (int off = 16; off > 0; off >>= 1)
#pragma unroll
        for (int e = 0; e < E_; e++)
            acc[e] += __shfl_down_sync(0xFFFFFFFFu, acc[e], off);
    if (lane == 0) {
        float best = acc[0] + bg[0];
        int bi = 0;
#pragma unroll
        for (int e = 1; e < E_; e++) {
            float v = acc[e] + bg[e];
            if (v > best) { best = v; bi = e; }
        }
        int p = atomicAdd(&g_counts[bi], 1);
        g_expert[tok] = bi;
        g_pos[tok]    = p;
    }
}

// ---------------- assign compacted rows ----------------
__global__ void assign_kernel() {
    int t = blockIdx.x * blockDim.x + threadIdx.x;
    if (t >= N_) return;
    int e = g_expert[t];
    int r = expert_off(e) + g_pos[t];
    g_row2tok[r] = t;
}

// =====================================================================
// fp16 GEMM core, BK=32: 256 thr, 8 warps (2x4), warp tile 64x32.
// Per iter: 2 x k16 sub-blocks, each 6 LDSM + 16 HMMA per warp;
// ONE __syncthreads per 32 k-halves. 3-stage ring, wait_group 1.
// Needs in scope: tid, ap0/ap1 (A, k-contig, rows t>>2 and +64),
// bp0/bp1 (B k-rows t>>4 and +16). Dynamic smem SMEM_B bytes.
// =====================================================================
#define GEMM_CORE(NK, CWIDTH)                                                     \
    extern __shared__ __align__(16) char smem_raw[];                              \
    const int lane = tid & 31;                                                    \
    const int warp = tid >> 5;                                                    \
    const int wm   = warp >> 2;                                                   \
    const int wn   = warp & 3;                                                    \
    const uint32_t sA0 = (uint32_t)__cvta_generic_to_shared(smem_raw);            \
    const uint32_t sB0 = sA0 + BBASE_B;                                           \
    const uint32_t dstA0 = sA0 + (((tid >> 2) * A_STRIDE + (tid & 3) * 8)) * 2;   \
    const uint32_t dstA1 = dstA0 + 64 * A_STRIDE * 2;                             \
    const uint32_t dstB0 = sB0 + (((tid >> 4) * B_STRIDE + (tid & 15) * 8)) * 2;  \
    const uint32_t dstB1 = dstB0 + 16 * B_STRIDE * 2;                             \
    uint32_t adA[4], adB[2];                                                      \
    _Pragma("unroll")                                                             \
    for (int mt = 0; mt < 4; mt++)                                                \
        adA[mt] = sA0 + (((wm * 64 + mt * 16 + (lane & 15)) * A_STRIDE            \
                          + (lane >> 4) * 8)) * 2;                                \
    _Pragma("unroll")                                                             \
    for (int pr = 0; pr < 2; pr++) {                                              \
        const int j = lane >> 3;                                                  \
        const int kr = (j & 1) * 8 + (lane & 7);                                  \
        const int ncl = wn * 32 + pr * 16 + (j >> 1) * 8;                         \
        adB[pr] = sB0 + (kr * B_STRIDE + ncl) * 2;                                \
    }                                                                             \
    float acc[4][4][4];                                                           \
    _Pragma("unroll") for (int i = 0; i < 4; i++)                                 \
    _Pragma("unroll") for (int j = 0; j < 4; j++)                                 \
    _Pragma("unroll") for (int q = 0; q < 4; q++) acc[i][j][q] = 0.f;             \
    _Pragma("unroll")                                                             \
    for (int s = 0; s < 2; s++) {                                                 \
        cp_async16_s(dstA0 + s * ASTG_B, ap0 + (size_t)s * BK);                   \
        cp_async16_s(dstA1 + s * ASTG_B, ap1 + (size_t)s * BK);                   \
        cp_async16_s(dstB0 + s * BSTG_B, bp0 + (size_t)s * BK * (CWIDTH));        \
        cp_async16_s(dstB1 + s * BSTG_B, bp1 + (size_t)s * BK * (CWIDTH));        \
        cp_commit();                                                              \
    }                                                                             \
    for (int it = 0; it < (NK); ++it) {                                           \
        cp_wait1();                                                               \
        __syncthreads();                                                          \
        if (it + 2 < (NK)) {                                                      \
            const int s = (it + 2) % NSTG;                                        \
            cp_async16_s(dstA0 + s * ASTG_B, ap0 + (size_t)(it + 2) * BK);        \
            cp_async16_s(dstA1 + s * ASTG_B, ap1 + (size_t)(it + 2) * BK);        \
            cp_async16_s(dstB0 + s * BSTG_B, bp0 + (size_t)(it + 2) * BK * (CWIDTH)); \
            cp_async16_s(dstB1 + s * BSTG_B, bp1 + (size_t)(it + 2) * BK * (CWIDTH)); \
        }                                                                         \
        cp_commit();                                                              \
        const int cur = it % NSTG;                                                \
        const uint32_t oA = cur * ASTG_B;                                         \
        const uint32_t oB = cur * BSTG_B;                                         \
        _Pragma("unroll")                                                         \
        for (int sub = 0; sub < 2; ++sub) {                                       \
            const uint32_t sAoff = oA + sub * 32;   /* 16 halves */               \
            const uint32_t sBoff = oB + sub * 16 * B_STRIDE * 2;                  \
            uint32_t a[4][4], bb[2][4];                                           \
            _Pragma("unroll")                                                     \
            for (int mt = 0; mt < 4; mt++) ldsm_x4(a[mt], adA[mt] + sAoff);       \
            _Pragma("unroll")                                                     \
            for (int pr = 0; pr < 2; pr++) ldsm_x4_t(bb[pr], adB[pr] + sBoff);    \
            _Pragma("unroll")                                                     \
            for (int mt = 0; mt < 4; mt++)                                        \
            _Pragma("unroll")                                                     \
            for (int nt = 0; nt < 4; nt++)                                        \
                mma_f16(acc[mt][nt], a[mt], bb[nt >> 1][(nt & 1) * 2],            \
                        bb[nt >> 1][(nt & 1) * 2 + 1]);                           \
        }                                                                         \
    }

// ---------------- GEMM1: H = fp16(relu(x @ W1 + b1)) ----------------
__global__ __launch_bounds__(256, 2)
void gemm1_tc(const float* __restrict__ b1) {
    const int e   = blockIdx.z;
    const int cnt = g_counts[e];
    const int m0  = blockIdx.y * 128;
    if (m0 >= cnt) return;
    const int off = expert_off(e);
    const int n0  = blockIdx.x * 128;
    const int tid = threadIdx.x;

    const int ar0 = imin(m0 + (tid >> 2), cnt - 1);
    const int ar1 = imin(m0 + (tid >> 2) + 64, cnt - 1);
    const __half* ap0 = g_xh + (size_t)g_row2tok[off + ar0] * D_ + (tid & 3) * 8;
    const __half* ap1 = g_xh + (size_t)g_row2tok[off + ar1] * D_ + (tid & 3) * 8;
    const __half* bp0 = g_W1h + (size_t)e * D_ * F_ + (size_t)(tid >> 4) * F_ + n0 + (tid & 15) * 8;
    const __half* bp1 = bp0 + (size_t)16 * F_;

    GEMM_CORE(D_ / BK, F_)     // 16 iters

    const float* b1e = b1 + (size_t)e * F_;
#pragma unroll
    for (int mt = 0; mt < 4; ++mt) {
        const int rb = m0 + wm * 64 + mt * 16 + (lane >> 2);
#pragma unroll
        for (int half = 0; half < 2; ++half) {
            const int r = rb + half * 8;
            if (r < cnt) {
                __half* Hrow = g_H + (size_t)(off + r) * F_;
#pragma unroll
                for (int nt = 0; nt < 4; ++nt) {
                    const int c = n0 + wn * 32 + nt * 8 + (lane & 3) * 2;
                    float v0 = fmaxf(acc[mt][nt][half * 2 + 0] + b1e[c],     0.f);
                    float v1 = fmaxf(acc[mt][nt][half * 2 + 1] + b1e[c + 1], 0.f);
                    __half2 h = __floats2half2_rn(v0, v1);
                    *reinterpret_cast<__half2*>(Hrow + c) = h;
                }
            }
        }
    }
}

// ---------------- GEMM2 (split-K=2, fused reduce): out = H @ W2 + b2 ----------
__global__ __launch_bounds__(256, 2)
void gemm2_tc(const float* __restrict__ b2, float* __restrict__ out) {
    const int e   = blockIdx.z;
    const int cnt = g_counts[e];
    const int m0  = blockIdx.y * 128;
    if (m0 >= cnt) return;
    const int off = expert_off(e);
    const int kp  = blockIdx.x >> 2;
    const int ni  = blockIdx.x & 3;
    const int n0  = ni * 128;
    const int kbase = kp * (F_ / KSPLIT);
    const int tid = threadIdx.x;
    const int tileid = (e * (N_ / 128) + blockIdx.y) * NTILE2 + ni;

    const int ar0 = imin(m0 + (tid >> 2), cnt - 1);
    const int ar1 = imin(m0 + (tid >> 2) + 64, cnt - 1);
    const __half* ap0 = g_H + (size_t)(off + ar0) * F_ + kbase + (tid & 3) * 8;
    const __half* ap1 = g_H + (size_t)(off + ar1) * F_ + kbase + (tid & 3) * 8;
    const __half* bp0 = g_W2h + (size_t)e * D_ * F_ + (size_t)(kbase + (tid >> 4)) * D_ + n0 + (tid & 15) * 8;
    const __half* bp1 = bp0 + (size_t)16 * D_;

    GEMM_CORE((F_ / KSPLIT) / BK, D_)    // 32 iters

    // 1) stage my partial
    float* part = g_part[kp];
#pragma unroll
    for (int mt = 0; mt < 4; ++mt) {
        const int rb = m0 + wm * 64 + mt * 16 + (lane >> 2);
#pragma unroll
        for (int half = 0; half < 2; ++half) {
            const int r = rb + half * 8;
            if (r < cnt) {
                float* prow = part + (size_t)(off + r) * D_;
#pragma unroll
                for (int nt = 0; nt < 4; ++nt) {
                    const int c = n0 + wn * 32 + nt * 8 + (lane & 3) * 2;
                    float2 o;
                    o.x = acc[mt][nt][half * 2 + 0];
                    o.y = acc[mt][nt][half * 2 + 1];
                    *reinterpret_cast<float2*>(prow + c) = o;
                }
            }
        }
    }

    // 2) handshake: second finisher combines
    __threadfence();
    __syncthreads();
    __shared__ int s_old;
    if (tid == 0) s_old = atomicAdd(&g_flags[tileid], 1);
    __syncthreads();
    if (s_old != 1) return;
    __threadfence();

    const float* other = g_part[1 - kp];
    const float* b2e = b2 + (size_t)e * D_;
#pragma unroll
    for (int mt = 0; mt < 4; ++mt) {
        const int rb = m0 + wm * 64 + mt * 16 + (lane >> 2);
#pragma unroll
        for (int half = 0; half < 2; ++half) {
            const int r = rb + half * 8;
            if (r < cnt) {
                const int tok = g_row2tok[off + r];
                const float* orow = other + (size_t)(off + r) * D_;
                float* dst = out + (size_t)tok * D_;
#pragma unroll
                for (int nt = 0; nt < 4; ++nt) {
                    const int c = n0 + wn * 32 + nt * 8 + (lane & 3) * 2;
                    float2 p = *reinterpret_cast<const float2*>(orow + c);
                    float2 o;
                    o.x = (p.x + acc[mt][nt][half * 2 + 0]) + b2e[c];
                    o.y = (p.y + acc[mt][nt][half * 2 + 1]) + b2e[c + 1];
                    *reinterpret_cast<float2*>(dst + c) = o;
                }
            }
        }
    }
}

// ---------------- launch ----------------
extern "C" void kernel_launch(void* const* d_in, const int* in_sizes, int n_in,
                              void* d_out, int out_size) {
    const float* x  = (const float*)d_in[0];
    const float* Wg = (const float*)d_in[1];
    const float* bg = (const float*)d_in[2];
    const float* W1 = (const float*)d_in[3];
    const float* b1 = (const float*)d_in[4];
    const float* W2 = (const float*)d_in[5];
    const float* b2 = (const float*)d_in[6];
    float* out = (float*)d_out;

    cudaFuncSetAttribute(gemm1_tc, cudaFuncAttributeMaxDynamicSharedMemorySize, SMEM_B);
    cudaFuncSetAttribute(gemm2_tc, cudaFuncAttributeMaxDynamicSharedMemorySize, SMEM_B);

    void* counts_addr = nullptr;
    cudaGetSymbolAddress(&counts_addr, g_counts);
    cudaMemsetAsync(counts_addr, 0, E_ * sizeof(int));
    void* flags_addr = nullptr;
    cudaGetSymbolAddress(&flags_addr, g_flags);
    cudaMemsetAsync(flags_addr, 0, NFLAGS * sizeof(int));

    prep_gate_kernel<<<GATE_BLOCKS + PREP_BLOCKS, 256>>>(x, Wg, bg, W1, W2);
    assign_kernel<<<N_ / 256, 256>>>();

    dim3 g1(F_ / 128, N_ / 128, E_);            // (16, 32, 8)
    gemm1_tc<<<g1, 256, SMEM_B>>>(b1);

    dim3 g2(NTILE2 * KSPLIT, N_ / 128, E_);     // (8, 32, 8)
    gemm2_tc<<<g2, 256, SMEM_B>>>(b2, out);
}

// round 13
// speedup vs baseline: 1.4909x; 1.0228x over previous
#include <cuda_runtime.h>
#include <cuda_fp16.h>
#include <cstdint>

#define E_ 8
#define D_ 512
#define F_ 2048
#define N_ 4096
#define KSPLIT 2

#define BK 32                      // k halves per stage (2 x k16 sub-blocks)
#define NSTG 3

#define A_STRIDE 40                // halves; 20-word rows, LDSM conflict-free
#define B_STRIDE 136               // halves; LDSM conflict-free

#define ASTG_B (128 * A_STRIDE * 2)     // 10240 B per A stage
#define BSTG_B (32 * B_STRIDE * 2)      // 8704 B per B stage
#define BBASE_B (NSTG * ASTG_B)         // 30720
#define SMEM_B (BBASE_B + NSTG * BSTG_B)  // 56832

#define WSZ ((size_t)E_ * D_ * F_)
#define XSZ ((size_t)N_ * D_)

#define GATE_BLOCKS 512
#define PREP_BLOCKS 1184

#define NTILE2 4
#define NFLAGS (E_ * (N_ / 128) * NTILE2)

// ---------------- scratch (no allocations allowed) ----------------
__device__ int g_counts[E_];
__device__ int g_flags[NFLAGS];
__device__ int g_expert[N_];
__device__ int g_pos[N_];
__device__ int g_row2tok[N_];
__device__ __align__(16) __half g_W1h[WSZ];            // W1 natural [e][d][f], fp16
__device__ __align__(16) __half g_W2h[WSZ];            // W2 natural [e][f][d], fp16
__device__ __align__(16) __half g_xh[XSZ];             // x fp16
__device__ __align__(16) __half g_H[(size_t)N_ * F_];  // hidden fp16
__device__ __align__(16) float  g_part[KSPLIT][(size_t)N_ * D_];

// ---------------- helpers ----------------
__device__ __forceinline__ int imin(int a, int b) { return a < b ? a : b; }

__device__ __forceinline__ void cp_async16_s(uint32_t sm, const void* gm) {
    asm volatile("cp.async.cg.shared.global [%0], [%1], 16;" :: "r"(sm), "l"(gm));
}
__device__ __forceinline__ void cp_commit() { asm volatile("cp.async.commit_group;"); }
__device__ __forceinline__ void cp_wait1()  { asm volatile("cp.async.wait_group 1;"); }

__device__ __forceinline__ void ldsm_x4(uint32_t r[4], uint32_t addr) {
    asm volatile("ldmatrix.sync.aligned.m8n8.x4.shared.b16 {%0,%1,%2,%3}, [%4];"
                 : "=r"(r[0]), "=r"(r[1]), "=r"(r[2]), "=r"(r[3]) : "r"(addr));
}
__device__ __forceinline__ void ldsm_x4_t(uint32_t r[4], uint32_t addr) {
    asm volatile("ldmatrix.sync.aligned.m8n8.x4.trans.shared.b16 {%0,%1,%2,%3}, [%4];"
                 : "=r"(r[0]), "=r"(r[1]), "=r"(r[2]), "=r"(r[3]) : "r"(addr));
}

__device__ __forceinline__ void mma_f16(float c[4], const uint32_t a[4],
                                        uint32_t b0, uint32_t b1) {
    asm volatile(
        "mma.sync.aligned.m16n8k16.row.col.f32.f16.f16.f32 "
        "{%0,%1,%2,%3}, {%4,%5,%6,%7}, {%8,%9}, {%0,%1,%2,%3};"
        : "+f"(c[0]), "+f"(c[1]), "+f"(c[2]), "+f"(c[3])
        : "r"(a[0]), "r"(a[1]), "r"(a[2]), "r"(a[3]), "r"(b0), "r"(b1));
}

__device__ __forceinline__ int expert_off(int e) {
    int s = 0;
#pragma unroll
    for (int i = 0; i < E_; i++) if (i < e) s += g_counts[i];
    return s;
}

__device__ __forceinline__ void cvt_chunk(const float4* src, __half* dst, size_t j) {
    float4 v = src[j];
    __half2 h0 = __floats2half2_rn(v.x, v.y);
    __half2 h1 = __floats2half2_rn(v.z, v.w);
    reinterpret_cast<uint2*>(dst)[j] = make_uint2(*(uint32_t*)&h0, *(uint32_t*)&h1);
}

// ---------------- prep1: W1->fp16 convert + gate + x->fp16 ----------------
// gate blocks [0, GATE_BLOCKS); W1-convert blocks above.
__global__ void prep_gate_kernel(const float* __restrict__ x,
                                 const float* __restrict__ Wg,
                                 const float* __restrict__ bg,
                                 const float* __restrict__ W1) {
    if (blockIdx.x >= GATE_BLOCKS) {
        const size_t n1 = WSZ / 4;
        const size_t stride = (size_t)PREP_BLOCKS * blockDim.x;
        for (size_t i = (size_t)(blockIdx.x - GATE_BLOCKS) * blockDim.x + threadIdx.x;
             i < n1; i += stride)
            cvt_chunk((const float4*)W1, g_W1h, i);
        return;
    }
    int tok  = (blockIdx.x * blockDim.x + threadIdx.x) >> 5;
    int lane = threadIdx.x & 31;
    if (tok >= N_) return;
    const float4* xr = reinterpret_cast<const float4*>(x) + (size_t)tok * (D_ / 4);
    uint2* xo = reinterpret_cast<uint2*>(g_xh) + (size_t)tok * (D_ / 4);

    float acc[E_];
#pragma unroll
    for (int e = 0; e < E_; e++) acc[e] = 0.f;

#pragma unroll
    for (int q = 0; q < 4; q++) {
        int d4 = lane + q * 32;
        float4 v = xr[d4];
        __half2 h0 = __floats2half2_rn(v.x, v.y);
        __half2 h1 = __floats2half2_rn(v.z, v.w);
        xo[d4] = make_uint2(*(uint32_t*)&h0, *(uint32_t*)&h1);
        float vv[4] = {v.x, v.y, v.z, v.w};
#pragma unroll
        for (int t = 0; t < 4; t++) {
            const float4* w = reinterpret_cast<const float4*>(Wg + (size_t)(d4 * 4 + t) * E_);
            float4 w0 = w[0], w1 = w[1];
            acc[0] += vv[t] * w0.x; acc[1] += vv[t] * w0.y;
            acc[2] += vv[t] * w0.z; acc[3] += vv[t] * w0.w;
            acc[4] += vv[t] * w1.x; acc[5] += vv[t] * w1.y;
            acc[6] += vv[t] * w1.z; acc[7] += vv[t] * w1.w;
        }
    }
#pragma unroll
    for (int off = 16; off > 0; off >>= 1)
#pragma unroll
        for (int e = 0; e < E_; e++)
            acc[e] += __shfl_down_sync(0xFFFFFFFFu, acc[e], off);
    if (lane == 0) {
        float best = acc[0] + bg[0];
        int bi = 0;
#pragma unroll
        for (int e = 1; e < E_; e++) {
            float v = acc[e] + bg[e];
            if (v > best) { best = v; bi = e; }
        }
        int p = atomicAdd(&g_counts[bi], 1);
        g_expert[tok] = bi;
        g_pos[tok]    = p;
    }
}

// ---------------- assign compacted rows ----------------
__global__ void assign_kernel() {
    int t = blockIdx.x * blockDim.x + threadIdx.x;
    if (t >= N_) return;
    int e = g_expert[t];
    int r = expert_off(e) + g_pos[t];
    g_row2tok[r] = t;
}

// =====================================================================
// fp16 GEMM core, BK=32 (proven round-12 config): 256 thr, 8 warps (2x4),
// warp tile 64x32. 2 x k16 sub-blocks per iter, ONE __syncthreads per iter.
// 3-stage ring, wait_group 1. Dynamic smem SMEM_B bytes.
// =====================================================================
#define GEMM_CORE(NK, CWIDTH)                                                     \
    extern __shared__ __align__(16) char smem_raw[];                              \
    const int lane = tid & 31;                                                    \
    const int warp = tid >> 5;                                                    \
    const int wm   = warp >> 2;                                                   \
    const int wn   = warp & 3;                                                    \
    const uint32_t sA0 = (uint32_t)__cvta_generic_to_shared(smem_raw);            \
    const uint32_t sB0 = sA0 + BBASE_B;                                           \
    const uint32_t dstA0 = sA0 + (((tid >> 2) * A_STRIDE + (tid & 3) * 8)) * 2;   \
    const uint32_t dstA1 = dstA0 + 64 * A_STRIDE * 2;                             \
    const uint32_t dstB0 = sB0 + (((tid >> 4) * B_STRIDE + (tid & 15) * 8)) * 2;  \
    const uint32_t dstB1 = dstB0 + 16 * B_STRIDE * 2;                             \
    uint32_t adA[4], adB[2];                                                      \
    _Pragma("unroll")                                                             \
    for (int mt = 0; mt < 4; mt++)                                                \
        adA[mt] = sA0 + (((wm * 64 + mt * 16 + (lane & 15)) * A_STRIDE            \
                          + (lane >> 4) * 8)) * 2;                                \
    _Pragma("unroll")                                                             \
    for (int pr = 0; pr < 2; pr++) {                                              \
        const int j = lane >> 3;                                                  \
        const int kr = (j & 1) * 8 + (lane & 7);                                  \
        const int ncl = wn * 32 + pr * 16 + (j >> 1) * 8;                         \
        adB[pr] = sB0 + (kr * B_STRIDE + ncl) * 2;                                \
    }                                                                             \
    float acc[4][4][4];                                                           \
    _Pragma("unroll") for (int i = 0; i < 4; i++)                                 \
    _Pragma("unroll") for (int j = 0; j < 4; j++)                                 \
    _Pragma("unroll") for (int q = 0; q < 4; q++) acc[i][j][q] = 0.f;             \
    _Pragma("unroll")                                                             \
    for (int s = 0; s < 2; s++) {                                                 \
        cp_async16_s(dstA0 + s * ASTG_B, ap0 + (size_t)s * BK);                   \
        cp_async16_s(dstA1 + s * ASTG_B, ap1 + (size_t)s * BK);                   \
        cp_async16_s(dstB0 + s * BSTG_B, bp0 + (size_t)s * BK * (CWIDTH));        \
        cp_async16_s(dstB1 + s * BSTG_B, bp1 + (size_t)s * BK * (CWIDTH));        \
        cp_commit();                                                              \
    }                                                                             \
    for (int it = 0; it < (NK); ++it) {                                           \
        cp_wait1();                                                               \
        __syncthreads();                                                          \
        if (it + 2 < (NK)) {                                                      \
            const int s = (it + 2) % NSTG;                                        \
            cp_async16_s(dstA0 + s * ASTG_B, ap0 + (size_t)(it + 2) * BK);        \
            cp_async16_s(dstA1 + s * ASTG_B, ap1 + (size_t)(it + 2) * BK);        \
            cp_async16_s(dstB0 + s * BSTG_B, bp0 + (size_t)(it + 2) * BK * (CWIDTH)); \
            cp_async16_s(dstB1 + s * BSTG_B, bp1 + (size_t)(it + 2) * BK * (CWIDTH)); \
        }                                                                         \
        cp_commit();                                                              \
        const int cur = it % NSTG;                                                \
        const uint32_t oA = cur * ASTG_B;                                         \
        const uint32_t oB = cur * BSTG_B;                                         \
        _Pragma("unroll")                                                         \
        for (int sub = 0; sub < 2; ++sub) {                                       \
            const uint32_t sAoff = oA + sub * 32;                                 \
            const uint32_t sBoff = oB + sub * 16 * B_STRIDE * 2;                  \
            uint32_t a[4][4], bb[2][4];                                           \
            _Pragma("unroll")                                                     \
            for (int mt = 0; mt < 4; mt++) ldsm_x4(a[mt], adA[mt] + sAoff);       \
            _Pragma("unroll")                                                     \
            for (int pr = 0; pr < 2; pr++) ldsm_x4_t(bb[pr], adB[pr] + sBoff);    \
            _Pragma("unroll")                                                     \
            for (int mt = 0; mt < 4; mt++)                                        \
            _Pragma("unroll")                                                     \
            for (int nt = 0; nt < 4; nt++)                                        \
                mma_f16(acc[mt][nt], a[mt], bb[nt >> 1][(nt & 1) * 2],            \
                        bb[nt >> 1][(nt & 1) * 2 + 1]);                           \
        }                                                                         \
    }

// ---------------- GEMM1 + hidden W2 convert plane ----------------
// grid (16, 32, 9): z<8 -> GEMM blocks; z==8 -> W2 fp32->fp16 convert (512
// blocks, grid-stride). Converter runs concurrently on SM slots freed by the
// ~87% of GEMM blocks that early-exit; kernel completion boundary guarantees
// W2 is ready before gemm2 launches.
__global__ __launch_bounds__(256, 2)
void gemm1_tc(const float* __restrict__ b1, const float* __restrict__ W2) {
    const int tid = threadIdx.x;
    if (blockIdx.z == E_) {
        const size_t n2 = WSZ / 4;
        const size_t bid = (size_t)blockIdx.y * 16 + blockIdx.x;   // 0..511
        const size_t stride = (size_t)512 * 256;
        for (size_t i = bid * 256 + tid; i < n2; i += stride)
            cvt_chunk((const float4*)W2, g_W2h, i);
        return;
    }
    const int e   = blockIdx.z;
    const int cnt = g_counts[e];
    const int m0  = blockIdx.y * 128;
    if (m0 >= cnt) return;
    const int off = expert_off(e);
    const int n0  = blockIdx.x * 128;

    const int ar0 = imin(m0 + (tid >> 2), cnt - 1);
    const int ar1 = imin(m0 + (tid >> 2) + 64, cnt - 1);
    const __half* ap0 = g_xh + (size_t)g_row2tok[off + ar0] * D_ + (tid & 3) * 8;
    const __half* ap1 = g_xh + (size_t)g_row2tok[off + ar1] * D_ + (tid & 3) * 8;
    const __half* bp0 = g_W1h + (size_t)e * D_ * F_ + (size_t)(tid >> 4) * F_ + n0 + (tid & 15) * 8;
    const __half* bp1 = bp0 + (size_t)16 * F_;

    GEMM_CORE(D_ / BK, F_)     // 16 iters

    const float* b1e = b1 + (size_t)e * F_;
#pragma unroll
    for (int mt = 0; mt < 4; ++mt) {
        const int rb = m0 + wm * 64 + mt * 16 + (lane >> 2);
#pragma unroll
        for (int half = 0; half < 2; ++half) {
            const int r = rb + half * 8;
            if (r < cnt) {
                __half* Hrow = g_H + (size_t)(off + r) * F_;
#pragma unroll
                for (int nt = 0; nt < 4; ++nt) {
                    const int c = n0 + wn * 32 + nt * 8 + (lane & 3) * 2;
                    float v0 = fmaxf(acc[mt][nt][half * 2 + 0] + b1e[c],     0.f);
                    float v1 = fmaxf(acc[mt][nt][half * 2 + 1] + b1e[c + 1], 0.f);
                    __half2 h = __floats2half2_rn(v0, v1);
                    *reinterpret_cast<__half2*>(Hrow + c) = h;
                }
            }
        }
    }
}

// ---------------- GEMM2 (split-K=2, fused reduce): out = H @ W2 + b2 ----------
__global__ __launch_bounds__(256, 2)
void gemm2_tc(const float* __restrict__ b2, float* __restrict__ out) {
    const int e   = blockIdx.z;
    const int cnt = g_counts[e];
    const int m0  = blockIdx.y * 128;
    if (m0 >= cnt) return;
    const int off = expert_off(e);
    const int kp  = blockIdx.x >> 2;
    const int ni  = blockIdx.x & 3;
    const int n0  = ni * 128;
    const int kbase = kp * (F_ / KSPLIT);
    const int tid = threadIdx.x;
    const int tileid = (e * (N_ / 128) + blockIdx.y) * NTILE2 + ni;

    const int ar0 = imin(m0 + (tid >> 2), cnt - 1);
    const int ar1 = imin(m0 + (tid >> 2) + 64, cnt - 1);
    const __half* ap0 = g_H + (size_t)(off + ar0) * F_ + kbase + (tid & 3) * 8;
    const __half* ap1 = g_H + (size_t)(off + ar1) * F_ + kbase + (tid & 3) * 8;
    const __half* bp0 = g_W2h + (size_t)e * D_ * F_ + (size_t)(kbase + (tid >> 4)) * D_ + n0 + (tid & 15) * 8;
    const __half* bp1 = bp0 + (size_t)16 * D_;

    GEMM_CORE((F_ / KSPLIT) / BK, D_)    // 32 iters

    // 1) stage my partial
    float* part = g_part[kp];
#pragma unroll
    for (int mt = 0; mt < 4; ++mt) {
        const int rb = m0 + wm * 64 + mt * 16 + (lane >> 2);
#pragma unroll
        for (int half = 0; half < 2; ++half) {
            const int r = rb + half * 8;
            if (r < cnt) {
                float* prow = part + (size_t)(off + r) * D_;
#pragma unroll
                for (int nt = 0; nt < 4; ++nt) {
                    const int c = n0 + wn * 32 + nt * 8 + (lane & 3) * 2;
                    float2 o;
                    o.x = acc[mt][nt][half * 2 + 0];
                    o.y = acc[mt][nt][half * 2 + 1];
                    *reinterpret_cast<float2*>(prow + c) = o;
                }
            }
        }
    }

    // 2) handshake: second finisher combines
    __threadfence();
    __syncthreads();
    __shared__ int s_old;
    if (tid == 0) s_old = atomicAdd(&g_flags[tileid], 1);
    __syncthreads();
    if (s_old != 1) return;
    __threadfence();

    const float* other = g_part[1 - kp];
    const float* b2e = b2 + (size_t)e * D_;
#pragma unroll
    for (int mt = 0; mt < 4; ++mt) {
        const int rb = m0 + wm * 64 + mt * 16 + (lane >> 2);
#pragma unroll
        for (int half = 0; half < 2; ++half) {
            const int r = rb + half * 8;
            if (r < cnt) {
                const int tok = g_row2tok[off + r];
                const float* orow = other + (size_t)(off + r) * D_;
                float* dst = out + (size_t)tok * D_;
#pragma unroll
                for (int nt = 0; nt < 4; ++nt) {
                    const int c = n0 + wn * 32 + nt * 8 + (lane & 3) * 2;
                    float2 p = *reinterpret_cast<const float2*>(orow + c);
                    float2 o;
                    o.x = (p.x + acc[mt][nt][half * 2 + 0]) + b2e[c];
                    o.y = (p.y + acc[mt][nt][half * 2 + 1]) + b2e[c + 1];
                    *reinterpret_cast<float2*>(dst + c) = o;
                }
            }
        }
    }
}

// ---------------- launch ----------------
extern "C" void kernel_launch(void* const* d_in, const int* in_sizes, int n_in,
                              void* d_out, int out_size) {
    const float* x  = (const float*)d_in[0];
    const float* Wg = (const float*)d_in[1];
    const float* bg = (const float*)d_in[2];
    const float* W1 = (const float*)d_in[3];
    const float* b1 = (const float*)d_in[4];
    const float* W2 = (const float*)d_in[5];
    const float* b2 = (const float*)d_in[6];
    float* out = (float*)d_out;

    cudaFuncSetAttribute(gemm1_tc, cudaFuncAttributeMaxDynamicSharedMemorySize, SMEM_B);
    cudaFuncSetAttribute(gemm2_tc, cudaFuncAttributeMaxDynamicSharedMemorySize, SMEM_B);

    void* counts_addr = nullptr;
    cudaGetSymbolAddress(&counts_addr, g_counts);
    cudaMemsetAsync(counts_addr, 0, E_ * sizeof(int));
    void* flags_addr = nullptr;
    cudaGetSymbolAddress(&flags_addr, g_flags);
    cudaMemsetAsync(flags_addr, 0, NFLAGS * sizeof(int));

    prep_gate_kernel<<<GATE_BLOCKS + PREP_BLOCKS, 256>>>(x, Wg, bg, W1);
    assign_kernel<<<N_ / 256, 256>>>();

    dim3 g1(F_ / 128, N_ / 128, E_ + 1);        // (16, 32, 9): z==8 converts W2
    gemm1_tc<<<g1, 256, SMEM_B>>>(b1, W2);

    dim3 g2(NTILE2 * KSPLIT, N_ / 128, E_);     // (8, 32, 8)
    gemm2_tc<<<g2, 256, SMEM_B>>>(b2, out);
}

// round 14
// speedup vs baseline: 1.5044x; 1.0090x over previous
#include <cuda_runtime.h>
#include <cuda_fp16.h>
#include <cstdint>

#define E_ 8
#define D_ 512
#define F_ 2048
#define N_ 4096
#define KSPLIT 2

#define BK 32                      // k halves per stage (2 x k16 sub-blocks)
#define NSTG 3

#define A_STRIDE 40                // halves; 20-word rows, LDSM conflict-free
#define B_STRIDE 136               // halves; LDSM conflict-free

#define ASTG_B (128 * A_STRIDE * 2)     // 10240 B per A stage
#define BSTG_B (32 * B_STRIDE * 2)      // 8704 B per B stage
#define BBASE_B (NSTG * ASTG_B)         // 30720
#define SMEM_B (BBASE_B + NSTG * BSTG_B)  // 56832

#define WSZ ((size_t)E_ * D_ * F_)
#define XSZ ((size_t)N_ * D_)

#define GATE_BLOCKS 512
#define PREP_TOTAL 1184            // single wave: 512 gate + 672 convert

#define NTILE2 4
#define NFLAGS (E_ * (N_ / 128) * NTILE2)   // 1024

// ---------------- scratch (no allocations allowed) ----------------
// g_sync: [0..7] expert counts, [8] gate-done counter, [9..] gemm2 tile flags
__device__ int g_sync[9 + NFLAGS];
__device__ int g_expert[N_];
__device__ int g_pos[N_];
__device__ int g_row2tok[N_];
__device__ __align__(16) __half g_W1h[WSZ];            // W1 natural [e][d][f], fp16
__device__ __align__(16) __half g_W2h[WSZ];            // W2 natural [e][f][d], fp16
__device__ __align__(16) __half g_xh[XSZ];             // x fp16
__device__ __align__(16) __half g_H[(size_t)N_ * F_];  // hidden fp16
__device__ __align__(16) float  g_part[(size_t)N_ * D_];  // single partial buffer

// ---------------- helpers ----------------
__device__ __forceinline__ int imin(int a, int b) { return a < b ? a : b; }

__device__ __forceinline__ void cp_async16_s(uint32_t sm, const void* gm) {
    asm volatile("cp.async.cg.shared.global [%0], [%1], 16;" :: "r"(sm), "l"(gm));
}
__device__ __forceinline__ void cp_commit() { asm volatile("cp.async.commit_group;"); }
__device__ __forceinline__ void cp_wait1()  { asm volatile("cp.async.wait_group 1;"); }

__device__ __forceinline__ void ldsm_x4(uint32_t r[4], uint32_t addr) {
    asm volatile("ldmatrix.sync.aligned.m8n8.x4.shared.b16 {%0,%1,%2,%3}, [%4];"
                 : "=r"(r[0]), "=r"(r[1]), "=r"(r[2]), "=r"(r[3]) : "r"(addr));
}
__device__ __forceinline__ void ldsm_x4_t(uint32_t r[4], uint32_t addr) {
    asm volatile("ldmatrix.sync.aligned.m8n8.x4.trans.shared.b16 {%0,%1,%2,%3}, [%4];"
                 : "=r"(r[0]), "=r"(r[1]), "=r"(r[2]), "=r"(r[3]) : "r"(addr));
}

__device__ __forceinline__ void mma_f16(float c[4], const uint32_t a[4],
                                        uint32_t b0, uint32_t b1) {
    asm volatile(
        "mma.sync.aligned.m16n8k16.row.col.f32.f16.f16.f32 "
        "{%0,%1,%2,%3}, {%4,%5,%6,%7}, {%8,%9}, {%0,%1,%2,%3};"
        : "+f"(c[0]), "+f"(c[1]), "+f"(c[2]), "+f"(c[3])
        : "r"(a[0]), "r"(a[1]), "r"(a[2]), "r"(a[3]), "r"(b0), "r"(b1));
}

__device__ __forceinline__ int expert_off(int e) {
    int s = 0;
#pragma unroll
    for (int i = 0; i < E_; i++) if (i < e) s += g_sync[i];
    return s;
}

__device__ __forceinline__ void cvt_chunk(const float4* src, __half* dst, size_t j) {
    float4 v = src[j];
    __half2 h0 = __floats2half2_rn(v.x, v.y);
    __half2 h1 = __floats2half2_rn(v.z, v.w);
    reinterpret_cast<uint2*>(dst)[j] = make_uint2(*(uint32_t*)&h0, *(uint32_t*)&h1);
}

// ---------------- prep: W1->fp16 + gate + x->fp16 + in-kernel assign ----------
// blocks [0, GATE_BLOCKS): gate (8 tokens each). blocks [GATE_BLOCKS, PREP_TOTAL):
// W1 convert. Blocks 0..15 (wave-1 resident by dispatch order, so the spin is
// deadlock-free) wait for all gates then write the compacted row map.
__global__ void prep_gate_kernel(const float* __restrict__ x,
                                 const float* __restrict__ Wg,
                                 const float* __restrict__ bg,
                                 const float* __restrict__ W1) {
    const int bid = blockIdx.x;
    if (bid >= GATE_BLOCKS) {
        const size_t n1 = WSZ / 4;
        const size_t stride = (size_t)(PREP_TOTAL - GATE_BLOCKS) * blockDim.x;
        for (size_t i = (size_t)(bid - GATE_BLOCKS) * blockDim.x + threadIdx.x;
             i < n1; i += stride)
            cvt_chunk((const float4*)W1, g_W1h, i);
        return;
    }
    // ---- gate + x fp16 convert: one warp per token ----
    int tok  = (bid * blockDim.x + threadIdx.x) >> 5;
    int lane = threadIdx.x & 31;
    {
        const float4* xr = reinterpret_cast<const float4*>(x) + (size_t)tok * (D_ / 4);
        uint2* xo = reinterpret_cast<uint2*>(g_xh) + (size_t)tok * (D_ / 4);

        float acc[E_];
#pragma unroll
        for (int e = 0; e < E_; e++) acc[e] = 0.f;

#pragma unroll
        for (int q = 0; q < 4; q++) {
            int d4 = lane + q * 32;
            float4 v = xr[d4];
            __half2 h0 = __floats2half2_rn(v.x, v.y);
            __half2 h1 = __floats2half2_rn(v.z, v.w);
            xo[d4] = make_uint2(*(uint32_t*)&h0, *(uint32_t*)&h1);
            float vv[4] = {v.x, v.y, v.z, v.w};
#pragma unroll
            for (int t = 0; t < 4; t++) {
                const float4* w = reinterpret_cast<const float4*>(Wg + (size_t)(d4 * 4 + t) * E_);
                float4 w0 = w[0], w1 = w[1];
                acc[0] += vv[t] * w0.x; acc[1] += vv[t] * w0.y;
                acc[2] += vv[t] * w0.z; acc[3] += vv[t] * w0.w;
                acc[4] += vv[t] * w1.x; acc[5] += vv[t] * w1.y;
                acc[6] += vv[t] * w1.z; acc[7] += vv[t] * w1.w;
            }
        }
#pragma unroll
        for (int off = 16; off > 0; off >>= 1)
#pragma unroll
            for (int e = 0; e < E_; e++)
                acc[e] += __shfl_down_sync(0xFFFFFFFFu, acc[e], off);
        if (lane == 0) {
            float best = acc[0] + bg[0];
            int bi = 0;
#pragma unroll
            for (int e = 1; e < E_; e++) {
                float v = acc[e] + bg[e];
                if (v > best) { best = v; bi = e; }
            }
            int p = atomicAdd(&g_sync[bi], 1);
            g_expert[tok] = bi;
            g_pos[tok]    = p;
            __threadfence();
            atomicAdd(&g_sync[8], 1);   // token gated
        }
    }

    // ---- blocks 0..15: wait for all gates, then assign compacted rows ----
    if (bid < 16) {
        if (threadIdx.x == 0) {
            while (atomicAdd(&g_sync[8], 0) < N_) __nanosleep(64);
        }
        __syncthreads();
        __threadfence();
        int t = bid * 256 + threadIdx.x;     // 16*256 = 4096 tokens
        int e = g_expert[t];
        int r = expert_off(e) + g_pos[t];
        g_row2tok[r] = t;
    }
}

// =====================================================================
// fp16 GEMM core, BK=32 (proven config): 256 thr, 8 warps (2x4),
// warp tile 64x32. 2 x k16 sub-blocks per iter, ONE __syncthreads per iter.
// 3-stage ring, wait_group 1. Dynamic smem SMEM_B bytes.
// =====================================================================
#define GEMM_CORE(NK, CWIDTH)                                                     \
    extern __shared__ __align__(16) char smem_raw[];                              \
    const int lane = tid & 31;                                                    \
    const int warp = tid >> 5;                                                    \
    const int wm   = warp >> 2;                                                   \
    const int wn   = warp & 3;                                                    \
    const uint32_t sA0 = (uint32_t)__cvta_generic_to_shared(smem_raw);            \
    const uint32_t sB0 = sA0 + BBASE_B;                                           \
    const uint32_t dstA0 = sA0 + (((tid >> 2) * A_STRIDE + (tid & 3) * 8)) * 2;   \
    const uint32_t dstA1 = dstA0 + 64 * A_STRIDE * 2;                             \
    const uint32_t dstB0 = sB0 + (((tid >> 4) * B_STRIDE + (tid & 15) * 8)) * 2;  \
    const uint32_t dstB1 = dstB0 + 16 * B_STRIDE * 2;                             \
    uint32_t adA[4], adB[2];                                                      \
    _Pragma("unroll")                                                             \
    for (int mt = 0; mt < 4; mt++)                                                \
        adA[mt] = sA0 + (((wm * 64 + mt * 16 + (lane & 15)) * A_STRIDE            \
                          + (lane >> 4) * 8)) * 2;                                \
    _Pragma("unroll")                                                             \
    for (int pr = 0; pr < 2; pr++) {                                              \
        const int j = lane >> 3;                                                  \
        const int kr = (j & 1) * 8 + (lane & 7);                                  \
        const int ncl = wn * 32 + pr * 16 + (j >> 1) * 8;                         \
        adB[pr] = sB0 + (kr * B_STRIDE + ncl) * 2;                                \
    }                                                                             \
    float acc[4][4][4];                                                           \
    _Pragma("unroll") for (int i = 0; i < 4; i++)                                 \
    _Pragma("unroll") for (int j = 0; j < 4; j++)                                 \
    _Pragma("unroll") for (int q = 0; q < 4; q++) acc[i][j][q] = 0.f;             \
    _Pragma("unroll")                                                             \
    for (int s = 0; s < 2; s++) {                                                 \
        cp_async16_s(dstA0 + s * ASTG_B, ap0 + (size_t)s * BK);                   \
        cp_async16_s(dstA1 + s * ASTG_B, ap1 + (size_t)s * BK);                   \
        cp_async16_s(dstB0 + s * BSTG_B, bp0 + (size_t)s * BK * (CWIDTH));        \
        cp_async16_s(dstB1 + s * BSTG_B, bp1 + (size_t)s * BK * (CWIDTH));        \
        cp_commit();                                                              \
    }                                                                             \
    for (int it = 0; it < (NK); ++it) {                                           \
        cp_wait1();                                                               \
        __syncthreads();                                                          \
        if (it + 2 < (NK)) {                                                      \
            const int s = (it + 2) % NSTG;                                        \
            cp_async16_s(dstA0 + s * ASTG_B, ap0 + (size_t)(it + 2) * BK);        \
            cp_async16_s(dstA1 + s * ASTG_B, ap1 + (size_t)(it + 2) * BK);        \
            cp_async16_s(dstB0 + s * BSTG_B, bp0 + (size_t)(it + 2) * BK * (CWIDTH)); \
            cp_async16_s(dstB1 + s * BSTG_B, bp1 + (size_t)(it + 2) * BK * (CWIDTH)); \
        }                                                                         \
        cp_commit();                                                              \
        const int cur = it % NSTG;                                                \
        const uint32_t oA = cur * ASTG_B;                                         \
        const uint32_t oB = cur * BSTG_B;                                         \
        _Pragma("unroll")                                                         \
        for (int sub = 0; sub < 2; ++sub) {                                       \
            const uint32_t sAoff = oA + sub * 32;                                 \
            const uint32_t sBoff = oB + sub * 16 * B_STRIDE * 2;                  \
            uint32_t a[4][4], bb[2][4];                                           \
            _Pragma("unroll")                                                     \
            for (int mt = 0; mt < 4; mt++) ldsm_x4(a[mt], adA[mt] + sAoff);       \
            _Pragma("unroll")                                                     \
            for (int pr = 0; pr < 2; pr++) ldsm_x4_t(bb[pr], adB[pr] + sBoff);    \
            _Pragma("unroll")                                                     \
            for (int mt = 0; mt < 4; mt++)                                        \
            _Pragma("unroll")                                                     \
            for (int nt = 0; nt < 4; nt++)                                        \
                mma_f16(acc[mt][nt], a[mt], bb[nt >> 1][(nt & 1) * 2],            \
                        bb[nt >> 1][(nt & 1) * 2 + 1]);                           \
        }                                                                         \
    }

// ---------------- GEMM1 + hidden W2 convert plane ----------------
__global__ __launch_bounds__(256, 2)
void gemm1_tc(const float* __restrict__ b1, const float* __restrict__ W2) {
    const int tid = threadIdx.x;
    if (blockIdx.z == E_) {
        const size_t n2 = WSZ / 4;
        const size_t bid = (size_t)blockIdx.y * 16 + blockIdx.x;   // 0..511
        const size_t stride = (size_t)512 * 256;
        for (size_t i = bid * 256 + tid; i < n2; i += stride)
            cvt_chunk((const float4*)W2, g_W2h, i);
        return;
    }
    const int e   = blockIdx.z;
    const int cnt = g_sync[e];
    const int m0  = blockIdx.y * 128;
    if (m0 >= cnt) return;
    const int off = expert_off(e);
    const int n0  = blockIdx.x * 128;

    const int ar0 = imin(m0 + (tid >> 2), cnt - 1);
    const int ar1 = imin(m0 + (tid >> 2) + 64, cnt - 1);
    const __half* ap0 = g_xh + (size_t)g_row2tok[off + ar0] * D_ + (tid & 3) * 8;
    const __half* ap1 = g_xh + (size_t)g_row2tok[off + ar1] * D_ + (tid & 3) * 8;
    const __half* bp0 = g_W1h + (size_t)e * D_ * F_ + (size_t)(tid >> 4) * F_ + n0 + (tid & 15) * 8;
    const __half* bp1 = bp0 + (size_t)16 * F_;

    GEMM_CORE(D_ / BK, F_)     // 16 iters

    const float* b1e = b1 + (size_t)e * F_;
#pragma unroll
    for (int mt = 0; mt < 4; ++mt) {
        const int rb = m0 + wm * 64 + mt * 16 + (lane >> 2);
#pragma unroll
        for (int half = 0; half < 2; ++half) {
            const int r = rb + half * 8;
            if (r < cnt) {
                __half* Hrow = g_H + (size_t)(off + r) * F_;
#pragma unroll
                for (int nt = 0; nt < 4; ++nt) {
                    const int c = n0 + wn * 32 + nt * 8 + (lane & 3) * 2;
                    float v0 = fmaxf(acc[mt][nt][half * 2 + 0] + b1e[c],     0.f);
                    float v1 = fmaxf(acc[mt][nt][half * 2 + 1] + b1e[c + 1], 0.f);
                    __half2 h = __floats2half2_rn(v0, v1);
                    *reinterpret_cast<__half2*>(Hrow + c) = h;
                }
            }
        }
    }
}

// ---------------- GEMM2 (split-K=2, single-partial fused reduce) ----------
// First finisher of each tile pair writes its partial to g_part (+fence,
// flag->2); second finisher spins (partner guaranteed executing -> no
// deadlock), reads it, writes out = partner + mine + b2. Commutative add ->
// deterministic either order.
__global__ __launch_bounds__(256, 2)
void gemm2_tc(const float* __restrict__ b2, float* __restrict__ out) {
    const int e   = blockIdx.z;
    const int cnt = g_sync[e];
    const int m0  = blockIdx.y * 128;
    if (m0 >= cnt) return;
    const int off = expert_off(e);
    const int kp  = blockIdx.x >> 2;
    const int ni  = blockIdx.x & 3;
    const int n0  = ni * 128;
    const int kbase = kp * (F_ / KSPLIT);
    const int tid = threadIdx.x;
    int* flag = &g_sync[9 + (e * (N_ / 128) + blockIdx.y) * NTILE2 + ni];

    const int ar0 = imin(m0 + (tid >> 2), cnt - 1);
    const int ar1 = imin(m0 + (tid >> 2) + 64, cnt - 1);
    const __half* ap0 = g_H + (size_t)(off + ar0) * F_ + kbase + (tid & 3) * 8;
    const __half* ap1 = g_H + (size_t)(off + ar1) * F_ + kbase + (tid & 3) * 8;
    const __half* bp0 = g_W2h + (size_t)e * D_ * F_ + (size_t)(kbase + (tid >> 4)) * D_ + n0 + (tid & 15) * 8;
    const __half* bp1 = bp0 + (size_t)16 * D_;

    GEMM_CORE((F_ / KSPLIT) / BK, D_)    // 32 iters

    __shared__ int s_old;
    if (tid == 0) s_old = atomicAdd(flag, 1);
    __syncthreads();

    if (s_old == 0) {
        // first finisher: stage partial, publish
#pragma unroll
        for (int mt = 0; mt < 4; ++mt) {
            const int rb = m0 + wm * 64 + mt * 16 + (lane >> 2);
#pragma unroll
            for (int half = 0; half < 2; ++half) {
                const int r = rb + half * 8;
                if (r < cnt) {
                    float* prow = g_part + (size_t)(off + r) * D_;
#pragma unroll
                    for (int nt = 0; nt < 4; ++nt) {
                        const int c = n0 + wn * 32 + nt * 8 + (lane & 3) * 2;
                        float2 o;
                        o.x = acc[mt][nt][half * 2 + 0];
                        o.y = acc[mt][nt][half * 2 + 1];
                        *reinterpret_cast<float2*>(prow + c) = o;
                    }
                }
            }
        }
        __threadfence();
        __syncthreads();
        if (tid == 0) atomicAdd(flag, 1);   // -> 2: data visible
        return;
    }

    // second finisher: wait for partner's partial, combine, write out
    if (tid == 0) {
        while (atomicAdd(flag, 0) < 2) __nanosleep(32);
    }
    __syncthreads();
    __threadfence();

    const float* b2e = b2 + (size_t)e * D_;
#pragma unroll
    for (int mt = 0; mt < 4; ++mt) {
        const int rb = m0 + wm * 64 + mt * 16 + (lane >> 2);
#pragma unroll
        for (int half = 0; half < 2; ++half) {
            const int r = rb + half * 8;
            if (r < cnt) {
                const int tok = g_row2tok[off + r];
                const float* prow = g_part + (size_t)(off + r) * D_;
                float* dst = out + (size_t)tok * D_;
#pragma unroll
                for (int nt = 0; nt < 4; ++nt) {
                    const int c = n0 + wn * 32 + nt * 8 + (lane & 3) * 2;
                    float2 p = *reinterpret_cast<const float2*>(prow + c);
                    float2 o;
                    o.x = (p.x + acc[mt][nt][half * 2 + 0]) + b2e[c];
                    o.y = (p.y + acc[mt][nt][half * 2 + 1]) + b2e[c + 1];
                    *reinterpret_cast<float2*>(dst + c) = o;
                }
            }
        }
    }
}

// ---------------- launch ----------------
extern "C" void kernel_launch(void* const* d_in, const int* in_sizes, int n_in,
                              void* d_out, int out_size) {
    const float* x  = (const float*)d_in[0];
    const float* Wg = (const float*)d_in[1];
    const float* bg = (const float*)d_in[2];
    const float* W1 = (const float*)d_in[3];
    const float* b1 = (const float*)d_in[4];
    const float* W2 = (const float*)d_in[5];
    const float* b2 = (const float*)d_in[6];
    float* out = (float*)d_out;

    cudaFuncSetAttribute(gemm1_tc, cudaFuncAttributeMaxDynamicSharedMemorySize, SMEM_B);
    cudaFuncSetAttribute(gemm2_tc, cudaFuncAttributeMaxDynamicSharedMemorySize, SMEM_B);

    // zero all sync state (counts + gate-done + tile flags) in one memset node
    void* sync_addr = nullptr;
    cudaGetSymbolAddress(&sync_addr, g_sync);
    cudaMemsetAsync(sync_addr, 0, (9 + NFLAGS) * sizeof(int));

    prep_gate_kernel<<<PREP_TOTAL, 256>>>(x, Wg, bg, W1);

    dim3 g1(F_ / 128, N_ / 128, E_ + 1);        // (16, 32, 9): z==8 converts W2
    gemm1_tc<<<g1, 256, SMEM_B>>>(b1, W2);

    dim3 g2(NTILE2 * KSPLIT, N_ / 128, E_);     // (8, 32, 8)
    gemm2_tc<<<g2, 256, SMEM_B>>>(b2, out);
}

// round 15
// speedup vs baseline: 1.6379x; 1.0888x over previous
#include <cuda_runtime.h>
#include <cuda_fp16.h>
#include <cstdint>

#define E_ 8
#define D_ 512
#define F_ 2048
#define N_ 4096
#define KSPLIT 2

#define BK 32                      // k halves per stage (2 x k16 sub-blocks)
#define NSTG 3

#define A_STRIDE 40                // halves; 20-word rows, LDSM conflict-free
#define B_STRIDE 136               // halves; LDSM conflict-free

#define ASTG_B (128 * A_STRIDE * 2)     // 10240 B per A stage
#define BSTG_B (32 * B_STRIDE * 2)      // 8704 B per B stage
#define BBASE_B (NSTG * ASTG_B)         // 30720
#define SMEM_B (BBASE_B + NSTG * BSTG_B)  // 56832

#define WSZ ((size_t)E_ * D_ * F_)
#define XSZ ((size_t)N_ * D_)

#define GATE_BLOCKS 512
#define PREP_TOTAL 1184            // single wave: 512 gate + 672 convert

#define NTILE2 4
#define NFLAGS (E_ * (N_ / 128) * NTILE2)   // 1024

// ---------------- scratch (no allocations allowed) ----------------
// g_sync: [0..7] expert counts, [8] gate-done counter, [9..] gemm2 tile flags
__device__ int g_sync[9 + NFLAGS];
__device__ int g_expert[N_];
__device__ int g_pos[N_];
__device__ int g_row2tok[N_];
__device__ __align__(16) __half g_W1h[WSZ];            // W1 natural [e][d][f], fp16
__device__ __align__(16) __half g_W2h[WSZ];            // W2 natural [e][f][d], fp16
__device__ __align__(16) __half g_xh[XSZ];             // x fp16
__device__ __align__(16) __half g_H[(size_t)N_ * F_];  // hidden fp16
__device__ __align__(16) float  g_part[(size_t)N_ * D_];  // single partial buffer

// ---------------- helpers ----------------
__device__ __forceinline__ int imin(int a, int b) { return a < b ? a : b; }

__device__ __forceinline__ void cp_async16_s(uint32_t sm, const void* gm) {
    asm volatile("cp.async.cg.shared.global [%0], [%1], 16;" :: "r"(sm), "l"(gm));
}
__device__ __forceinline__ void cp_commit() { asm volatile("cp.async.commit_group;"); }
__device__ __forceinline__ void cp_wait1()  { asm volatile("cp.async.wait_group 1;"); }

__device__ __forceinline__ void ldsm_x4(uint32_t r[4], uint32_t addr) {
    asm volatile("ldmatrix.sync.aligned.m8n8.x4.shared.b16 {%0,%1,%2,%3}, [%4];"
                 : "=r"(r[0]), "=r"(r[1]), "=r"(r[2]), "=r"(r[3]) : "r"(addr));
}
__device__ __forceinline__ void ldsm_x4_t(uint32_t r[4], uint32_t addr) {
    asm volatile("ldmatrix.sync.aligned.m8n8.x4.trans.shared.b16 {%0,%1,%2,%3}, [%4];"
                 : "=r"(r[0]), "=r"(r[1]), "=r"(r[2]), "=r"(r[3]) : "r"(addr));
}

__device__ __forceinline__ void mma_f16(float c[4], const uint32_t a[4],
                                        uint32_t b0, uint32_t b1) {
    asm volatile(
        "mma.sync.aligned.m16n8k16.row.col.f32.f16.f16.f32 "
        "{%0,%1,%2,%3}, {%4,%5,%6,%7}, {%8,%9}, {%0,%1,%2,%3};"
        : "+f"(c[0]), "+f"(c[1]), "+f"(c[2]), "+f"(c[3])
        : "r"(a[0]), "r"(a[1]), "r"(a[2]), "r"(a[3]), "r"(b0), "r"(b1));
}

__device__ __forceinline__ int expert_off(int e) {
    int s = 0;
#pragma unroll
    for (int i = 0; i < E_; i++) if (i < e) s += g_sync[i];
    return s;
}

__device__ __forceinline__ void cvt_chunk(const float4* src, __half* dst, size_t j) {
    float4 v = src[j];
    __half2 h0 = __floats2half2_rn(v.x, v.y);
    __half2 h1 = __floats2half2_rn(v.z, v.w);
    reinterpret_cast<uint2*>(dst)[j] = make_uint2(*(uint32_t*)&h0, *(uint32_t*)&h1);
}

// MLP-4 converter: batch 4 independent loads before converting/storing
__device__ __forceinline__ void cvt_range(const float4* src, __half* dst,
                                          size_t i0, size_t stride, size_t n) {
    size_t i = i0;
    for (; i + 3 * stride < n; i += 4 * stride) {
        float4 v0 = src[i];
        float4 v1 = src[i + stride];
        float4 v2 = src[i + 2 * stride];
        float4 v3 = src[i + 3 * stride];
        __half2 a0 = __floats2half2_rn(v0.x, v0.y), a1 = __floats2half2_rn(v0.z, v0.w);
        __half2 b0 = __floats2half2_rn(v1.x, v1.y), b1 = __floats2half2_rn(v1.z, v1.w);
        __half2 c0 = __floats2half2_rn(v2.x, v2.y), c1 = __floats2half2_rn(v2.z, v2.w);
        __half2 d0 = __floats2half2_rn(v3.x, v3.y), d1 = __floats2half2_rn(v3.z, v3.w);
        reinterpret_cast<uint2*>(dst)[i]              = make_uint2(*(uint32_t*)&a0, *(uint32_t*)&a1);
        reinterpret_cast<uint2*>(dst)[i + stride]     = make_uint2(*(uint32_t*)&b0, *(uint32_t*)&b1);
        reinterpret_cast<uint2*>(dst)[i + 2 * stride] = make_uint2(*(uint32_t*)&c0, *(uint32_t*)&c1);
        reinterpret_cast<uint2*>(dst)[i + 3 * stride] = make_uint2(*(uint32_t*)&d0, *(uint32_t*)&d1);
    }
    for (; i < n; i += stride) cvt_chunk(src, dst, i);
}

// ---------------- prep: W1->fp16 + gate (smem Wg) + x->fp16 + assign ----------
__global__ void prep_gate_kernel(const float* __restrict__ x,
                                 const float* __restrict__ Wg,
                                 const float* __restrict__ bg,
                                 const float* __restrict__ W1) {
    const int bid = blockIdx.x;
    if (bid >= GATE_BLOCKS) {
        cvt_range((const float4*)W1, g_W1h,
                  (size_t)(bid - GATE_BLOCKS) * blockDim.x + threadIdx.x,
                  (size_t)(PREP_TOTAL - GATE_BLOCKS) * blockDim.x, WSZ / 4);
        return;
    }
    // ---- gate: Wg staged in smem as [t][d4][e] (word = t*1024 + d4*8 + e) ----
    __shared__ float sWg[4096];     // 16 KB
    {
        const float4* wg4 = reinterpret_cast<const float4*>(Wg);
#pragma unroll
        for (int k = 0; k < 4; k++) {
            int j = threadIdx.x + k * 256;        // 0..1023 float4 chunks
            float4 v = wg4[j];                    // coalesced
            int d  = j >> 1;
            int e0 = (j & 1) * 4;
            int t  = d & 3, d4 = d >> 2;
            *reinterpret_cast<float4*>(&sWg[t * 1024 + d4 * 8 + e0]) = v;
        }
    }
    __syncthreads();

    int tok  = (bid * blockDim.x + threadIdx.x) >> 5;
    int lane = threadIdx.x & 31;
    {
        const float4* xr = reinterpret_cast<const float4*>(x) + (size_t)tok * (D_ / 4);
        uint2* xo = reinterpret_cast<uint2*>(g_xh) + (size_t)tok * (D_ / 4);

        float acc[E_];
#pragma unroll
        for (int e = 0; e < E_; e++) acc[e] = 0.f;

#pragma unroll
        for (int q = 0; q < 4; q++) {
            int d4 = lane + q * 32;
            float4 v = xr[d4];
            __half2 h0 = __floats2half2_rn(v.x, v.y);
            __half2 h1 = __floats2half2_rn(v.z, v.w);
            xo[d4] = make_uint2(*(uint32_t*)&h0, *(uint32_t*)&h1);
            float vv[4] = {v.x, v.y, v.z, v.w};
#pragma unroll
            for (int t = 0; t < 4; t++) {
                const float* wrow = &sWg[t * 1024 + d4 * 8];
                float4 w0 = *reinterpret_cast<const float4*>(wrow);
                float4 w1 = *reinterpret_cast<const float4*>(wrow + 4);
                acc[0] += vv[t] * w0.x; acc[1] += vv[t] * w0.y;
                acc[2] += vv[t] * w0.z; acc[3] += vv[t] * w0.w;
                acc[4] += vv[t] * w1.x; acc[5] += vv[t] * w1.y;
                acc[6] += vv[t] * w1.z; acc[7] += vv[t] * w1.w;
            }
        }
#pragma unroll
        for (int off = 16; off > 0; off >>= 1)
#pragma unroll
            for (int e = 0; e < E_; e++)
                acc[e] += __shfl_down_sync(0xFFFFFFFFu, acc[e], off);
        if (lane == 0) {
            float best = acc[0] + bg[0];
            int bi = 0;
#pragma unroll
            for (int e = 1; e < E_; e++) {
                float v = acc[e] + bg[e];
                if (v > best) { best = v; bi = e; }
            }
            int p = atomicAdd(&g_sync[bi], 1);
            g_expert[tok] = bi;
            g_pos[tok]    = p;
            __threadfence();
            atomicAdd(&g_sync[8], 1);   // token gated
        }
    }

    // ---- blocks 0..15 (wave-1 resident): wait for all gates, assign rows ----
    if (bid < 16) {
        if (threadIdx.x == 0) {
            while (atomicAdd(&g_sync[8], 0) < N_) __nanosleep(64);
        }
        __syncthreads();
        __threadfence();
        int t = bid * 256 + threadIdx.x;
        int e = g_expert[t];
        int r = expert_off(e) + g_pos[t];
        g_row2tok[r] = t;
    }
}

// =====================================================================
// fp16 GEMM core, BK=32 (proven config): 256 thr, 8 warps (2x4),
// warp tile 64x32. 2 x k16 sub-blocks per iter, ONE __syncthreads per iter.
// 3-stage ring, wait_group 1. Dynamic smem SMEM_B bytes.
// =====================================================================
#define GEMM_CORE(NK, CWIDTH)                                                     \
    extern __shared__ __align__(16) char smem_raw[];                              \
    const int lane = tid & 31;                                                    \
    const int warp = tid >> 5;                                                    \
    const int wm   = warp >> 2;                                                   \
    const int wn   = warp & 3;                                                    \
    const uint32_t sA0 = (uint32_t)__cvta_generic_to_shared(smem_raw);            \
    const uint32_t sB0 = sA0 + BBASE_B;                                           \
    const uint32_t dstA0 = sA0 + (((tid >> 2) * A_STRIDE + (tid & 3) * 8)) * 2;   \
    const uint32_t dstA1 = dstA0 + 64 * A_STRIDE * 2;                             \
    const uint32_t dstB0 = sB0 + (((tid >> 4) * B_STRIDE + (tid & 15) * 8)) * 2;  \
    const uint32_t dstB1 = dstB0 + 16 * B_STRIDE * 2;                             \
    uint32_t adA[4], adB[2];                                                      \
    _Pragma("unroll")                                                             \
    for (int mt = 0; mt < 4; mt++)                                                \
        adA[mt] = sA0 + (((wm * 64 + mt * 16 + (lane & 15)) * A_STRIDE            \
                          + (lane >> 4) * 8)) * 2;                                \
    _Pragma("unroll")                                                             \
    for (int pr = 0; pr < 2; pr++) {                                              \
        const int j = lane >> 3;                                                  \
        const int kr = (j & 1) * 8 + (lane & 7);                                  \
        const int ncl = wn * 32 + pr * 16 + (j >> 1) * 8;                         \
        adB[pr] = sB0 + (kr * B_STRIDE + ncl) * 2;                                \
    }                                                                             \
    float acc[4][4][4];                                                           \
    _Pragma("unroll") for (int i = 0; i < 4; i++)                                 \
    _Pragma("unroll") for (int j = 0; j < 4; j++)                                 \
    _Pragma("unroll") for (int q = 0; q < 4; q++) acc[i][j][q] = 0.f;             \
    _Pragma("unroll")                                                             \
    for (int s = 0; s < 2; s++) {                                                 \
        cp_async16_s(dstA0 + s * ASTG_B, ap0 + (size_t)s * BK);                   \
        cp_async16_s(dstA1 + s * ASTG_B, ap1 + (size_t)s * BK);                   \
        cp_async16_s(dstB0 + s * BSTG_B, bp0 + (size_t)s * BK * (CWIDTH));        \
        cp_async16_s(dstB1 + s * BSTG_B, bp1 + (size_t)s * BK * (CWIDTH));        \
        cp_commit();                                                              \
    }                                                                             \
    for (int it = 0; it < (NK); ++it) {                                           \
        cp_wait1();                                                               \
        __syncthreads();                                                          \
        if (it + 2 < (NK)) {                                                      \
            const int s = (it + 2) % NSTG;                                        \
            cp_async16_s(dstA0 + s * ASTG_B, ap0 + (size_t)(it + 2) * BK);        \
            cp_async16_s(dstA1 + s * ASTG_B, ap1 + (size_t)(it + 2) * BK);        \
            cp_async16_s(dstB0 + s * BSTG_B, bp0 + (size_t)(it + 2) * BK * (CWIDTH)); \
            cp_async16_s(dstB1 + s * BSTG_B, bp1 + (size_t)(it + 2) * BK * (CWIDTH)); \
        }                                                                         \
        cp_commit();                                                              \
        const int cur = it % NSTG;                                                \
        const uint32_t oA = cur * ASTG_B;                                         \
        const uint32_t oB = cur * BSTG_B;                                         \
        _Pragma("unroll")                                                         \
        for (int sub = 0; sub < 2; ++sub) {                                       \
            const uint32_t sAoff = oA + sub * 32;                                 \
            const uint32_t sBoff = oB + sub * 16 * B_STRIDE * 2;                  \
            uint32_t a[4][4], bb[2][4];                                           \
            _Pragma("unroll")                                                     \
            for (int mt = 0; mt < 4; mt++) ldsm_x4(a[mt], adA[mt] + sAoff);       \
            _Pragma("unroll")                                                     \
            for (int pr = 0; pr < 2; pr++) ldsm_x4_t(bb[pr], adB[pr] + sBoff);    \
            _Pragma("unroll")                                                     \
            for (int mt = 0; mt < 4; mt++)                                        \
            _Pragma("unroll")                                                     \
            for (int nt = 0; nt < 4; nt++)                                        \
                mma_f16(acc[mt][nt], a[mt], bb[nt >> 1][(nt & 1) * 2],            \
                        bb[nt >> 1][(nt & 1) * 2 + 1]);                           \
        }                                                                         \
    }

// ---------------- GEMM1 + hidden W2 convert plane ----------------
__global__ __launch_bounds__(256, 2)
void gemm1_tc(const float* __restrict__ b1, const float* __restrict__ W2) {
    const int tid = threadIdx.x;
    if (blockIdx.z == E_) {
        const size_t bid = (size_t)blockIdx.y * 16 + blockIdx.x;   // 0..511
        cvt_range((const float4*)W2, g_W2h, bid * 256 + tid,
                  (size_t)512 * 256, WSZ / 4);
        return;
    }
    const int e   = blockIdx.z;
    const int cnt = g_sync[e];
    const int m0  = blockIdx.y * 128;
    if (m0 >= cnt) return;
    const int off = expert_off(e);
    const int n0  = blockIdx.x * 128;

    const int ar0 = imin(m0 + (tid >> 2), cnt - 1);
    const int ar1 = imin(m0 + (tid >> 2) + 64, cnt - 1);
    const __half* ap0 = g_xh + (size_t)g_row2tok[off + ar0] * D_ + (tid & 3) * 8;
    const __half* ap1 = g_xh + (size_t)g_row2tok[off + ar1] * D_ + (tid & 3) * 8;
    const __half* bp0 = g_W1h + (size_t)e * D_ * F_ + (size_t)(tid >> 4) * F_ + n0 + (tid & 15) * 8;
    const __half* bp1 = bp0 + (size_t)16 * F_;

    GEMM_CORE(D_ / BK, F_)     // 16 iters

    const float* b1e = b1 + (size_t)e * F_;
#pragma unroll
    for (int mt = 0; mt < 4; ++mt) {
        const int rb = m0 + wm * 64 + mt * 16 + (lane >> 2);
#pragma unroll
        for (int half = 0; half < 2; ++half) {
            const int r = rb + half * 8;
            if (r < cnt) {
                __half* Hrow = g_H + (size_t)(off + r) * F_;
#pragma unroll
                for (int nt = 0; nt < 4; ++nt) {
                    const int c = n0 + wn * 32 + nt * 8 + (lane & 3) * 2;
                    float v0 = fmaxf(acc[mt][nt][half * 2 + 0] + b1e[c],     0.f);
                    float v1 = fmaxf(acc[mt][nt][half * 2 + 1] + b1e[c + 1], 0.f);
                    __half2 h = __floats2half2_rn(v0, v1);
                    *reinterpret_cast<__half2*>(Hrow + c) = h;
                }
            }
        }
    }
}

// ---------------- GEMM2 (split-K=2, single-partial fused reduce) ----------
__global__ __launch_bounds__(256, 2)
void gemm2_tc(const float* __restrict__ b2, float* __restrict__ out) {
    const int e   = blockIdx.z;
    const int cnt = g_sync[e];
    const int m0  = blockIdx.y * 128;
    if (m0 >= cnt) return;
    const int off = expert_off(e);
    const int kp  = blockIdx.x >> 2;
    const int ni  = blockIdx.x & 3;
    const int n0  = ni * 128;
    const int kbase = kp * (F_ / KSPLIT);
    const int tid = threadIdx.x;
    int* flag = &g_sync[9 + (e * (N_ / 128) + blockIdx.y) * NTILE2 + ni];

    const int ar0 = imin(m0 + (tid >> 2), cnt - 1);
    const int ar1 = imin(m0 + (tid >> 2) + 64, cnt - 1);
    const __half* ap0 = g_H + (size_t)(off + ar0) * F_ + kbase + (tid & 3) * 8;
    const __half* ap1 = g_H + (size_t)(off + ar1) * F_ + kbase + (tid & 3) * 8;
    const __half* bp0 = g_W2h + (size_t)e * D_ * F_ + (size_t)(kbase + (tid >> 4)) * D_ + n0 + (tid & 15) * 8;
    const __half* bp1 = bp0 + (size_t)16 * D_;

    GEMM_CORE((F_ / KSPLIT) / BK, D_)    // 32 iters

    __shared__ int s_old;
    if (tid == 0) s_old = atomicAdd(flag, 1);
    __syncthreads();

    if (s_old == 0) {
        // first finisher: stage partial, publish
#pragma unroll
        for (int mt = 0; mt < 4; ++mt) {
            const int rb = m0 + wm * 64 + mt * 16 + (lane >> 2);
#pragma unroll
            for (int half = 0; half < 2; ++half) {
                const int r = rb + half * 8;
                if (r < cnt) {
                    float* prow = g_part + (size_t)(off + r) * D_;
#pragma unroll
                    for (int nt = 0; nt < 4; ++nt) {
                        const int c = n0 + wn * 32 + nt * 8 + (lane & 3) * 2;
                        float2 o;
                        o.x = acc[mt][nt][half * 2 + 0];
                        o.y = acc[mt][nt][half * 2 + 1];
                        *reinterpret_cast<float2*>(prow + c) = o;
                    }
                }
            }
        }
        __threadfence();
        __syncthreads();
        if (tid == 0) atomicAdd(flag, 1);   // -> 2: data visible
        return;
    }

    // second finisher: wait for partner's partial, combine, write out
    if (tid == 0) {
        while (atomicAdd(flag, 0) < 2) __nanosleep(32);
    }
    __syncthreads();
    __threadfence();

    const float* b2e = b2 + (size_t)e * D_;
#pragma unroll
    for (int mt = 0; mt < 4; ++mt) {
        const int rb = m0 + wm * 64 + mt * 16 + (lane >> 2);
#pragma unroll
        for (int half = 0; half < 2; ++half) {
            const int r = rb + half * 8;
            if (r < cnt) {
                const int tok = g_row2tok[off + r];
                const float* prow = g_part + (size_t)(off + r) * D_;
                float* dst = out + (size_t)tok * D_;
#pragma unroll
                for (int nt = 0; nt < 4; ++nt) {
                    const int c = n0 + wn * 32 + nt * 8 + (lane & 3) * 2;
                    float2 p = *reinterpret_cast<const float2*>(prow + c);
                    float2 o;
                    o.x = (p.x + acc[mt][nt][half * 2 + 0]) + b2e[c];
                    o.y = (p.y + acc[mt][nt][half * 2 + 1]) + b2e[c + 1];
                    *reinterpret_cast<float2*>(dst + c) = o;
                }
            }
        }
    }
}

// ---------------- launch ----------------
extern "C" void kernel_launch(void* const* d_in, const int* in_sizes, int n_in,
                              void* d_out, int out_size) {
    const float* x  = (const float*)d_in[0];
    const float* Wg = (const float*)d_in[1];
    const float* bg = (const float*)d_in[2];
    const float* W1 = (const float*)d_in[3];
    const float* b1 = (const float*)d_in[4];
    const float* W2 = (const float*)d_in[5];
    const float* b2 = (const float*)d_in[6];
    float* out = (float*)d_out;

    cudaFuncSetAttribute(gemm1_tc, cudaFuncAttributeMaxDynamicSharedMemorySize, SMEM_B);
    cudaFuncSetAttribute(gemm2_tc, cudaFuncAttributeMaxDynamicSharedMemorySize, SMEM_B);

    void* sync_addr = nullptr;
    cudaGetSymbolAddress(&sync_addr, g_sync);
    cudaMemsetAsync(sync_addr, 0, (9 + NFLAGS) * sizeof(int));

    prep_gate_kernel<<<PREP_TOTAL, 256>>>(x, Wg, bg, W1);

    dim3 g1(F_ / 128, N_ / 128, E_ + 1);        // (16, 32, 9): z==8 converts W2
    gemm1_tc<<<g1, 256, SMEM_B>>>(b1, W2);

    dim3 g2(NTILE2 * KSPLIT, N_ / 128, E_);     // (8, 32, 8)
    gemm2_tc<<<g2, 256, SMEM_B>>>(b2, out);
}